// round 8
// baseline (speedup 1.0000x reference)
#include <cuda_runtime.h>
#include <stdint.h>
#include <math.h>

#define Bb 64
#define Tt 256
#define Dd 409
#define Hh 1024
#define G4 4096
#define TB 16384   // B*T
#define NCTA 128
#define WSTRIDE 514   // float2 stride for Ws rows (16B aligned, conflict-free)
#define HSTRIDE 34    // float2 stride for Hs rows (16B aligned)

typedef unsigned long long u64;

// All row indices are m = b*Tt + t (native [B,T,...] order)
__device__ float g_gx_enc[(size_t)TB*G4];
__device__ float g_gx_dec[(size_t)TB*G4];
__device__ float g_hs[(size_t)TB*Hh];
__device__ float g_hA[Bb*Hh];
__device__ float g_hB[Bb*Hh];
__device__ unsigned g_cnt = 0;
__device__ unsigned g_gen = 0;

__device__ __forceinline__ void fma2(u64& d, u64 a, u64 b){
    asm("fma.rn.f32x2 %0, %1, %2, %0;" : "+l"(d) : "l"(a), "l"(b));
}
__device__ __forceinline__ float hsum(u64 v){
    float x, y;
    asm("mov.b64 {%0,%1}, %2;" : "=f"(x), "=f"(y) : "l"(v));
    return x + y;
}

__global__ void k_zero1(float* a, int n){
    int i = blockIdx.x*blockDim.x + threadIdx.x;
    if (i < n) a[i] = 0.f;
}

// ---- gates from x: gx[m][n] = x_row(m) . Wih[n] + bias[n]   (unchanged; passed)
__global__ void k_gates(const float* __restrict__ x, const float* __restrict__ W,
                        const float* __restrict__ bias, float* __restrict__ gx,
                        int shifted){
    __shared__ float Asf[8*260];
    __shared__ float Bsf[8*132];

    int tid = threadIdx.x, tm = tid >> 4, tn = tid & 15;
    int m0 = blockIdx.y * 128, n0 = blockIdx.x * 64;

    u64 acc[8][4];
    #pragma unroll
    for (int i=0;i<8;i++)
        #pragma unroll
        for (int j=0;j<4;j++) acc[i][j] = 0ull;

    for (int kt = 0; kt < 26; kt++){
        int k0 = kt * 16;
        #pragma unroll
        for (int q = 0; q < 8; q++){
            int idx = tid + q*256, ml = idx >> 4, kk = idx & 15;
            int k = k0 + kk, m = m0 + ml;
            float v = 0.f;
            if (k < Dd){
                if (!shifted)            v = x[(size_t)m*Dd + k];
                else if ((m & 255) != 0) v = x[(size_t)(m-1)*Dd + k];
            }
            Asf[(kk>>1)*260 + 2*ml + (kk&1)] = v;
        }
        #pragma unroll
        for (int q = 0; q < 4; q++){
            int idx = tid + q*256, nl = idx >> 4, kk = idx & 15;
            int k = k0 + kk;
            float v = (k < Dd) ? W[(size_t)(n0 + nl)*Dd + k] : 0.f;
            Bsf[(kk>>1)*132 + 2*nl + (kk&1)] = v;
        }
        __syncthreads();
        const u64* Au = (const u64*)Asf;
        const u64* Bu = (const u64*)Bsf;
        #pragma unroll
        for (int kp = 0; kp < 8; kp++){
            u64 a[8], b[4];
            #pragma unroll
            for (int i=0;i<8;i++) a[i] = Au[kp*130 + i*16 + tm];
            #pragma unroll
            for (int j=0;j<4;j++) b[j] = Bu[kp*66 + j*16 + tn];
            #pragma unroll
            for (int i=0;i<8;i++)
                #pragma unroll
                for (int j=0;j<4;j++) fma2(acc[i][j], a[i], b[j]);
        }
        __syncthreads();
    }
    #pragma unroll
    for (int j=0;j<4;j++){
        int n = n0 + j*16 + tn;
        float bv = bias[n];
        #pragma unroll
        for (int i=0;i<8;i++)
            gx[(size_t)(m0 + i*16 + tm)*G4 + n] = hsum(acc[i][j]) + bv;
    }
}

// ---- grid-wide generation barrier ----
__device__ __forceinline__ void grid_bar(){
    __threadfence();
    __syncthreads();
    if (threadIdx.x == 0){
        volatile unsigned* vgen = &g_gen;
        unsigned gen = *vgen;
        unsigned t = atomicAdd(&g_cnt, 1u);
        if (t == NCTA - 1){
            g_cnt = 0;
            __threadfence();
            *vgen = gen + 1;
        } else {
            while (*vgen == gen) { }
        }
        __threadfence();
    }
    __syncthreads();
}

// ---- persistent recurrence: 512 steps, Whh smem-resident, 512 thr/CTA,
// float4 smem operand loads, double-buffered h tiles, c in registers.
__global__ void __launch_bounds__(512, 1) k_recur(
    const float* __restrict__ WhhE, const float* __restrict__ WhhD,
    float* __restrict__ lat)
{
    extern __shared__ float2 sm2[];
    float2* Ws2 = sm2;                              // 32 x WSTRIDE
    float2* Hs0 = sm2 + 32*WSTRIDE;                 // 64 x HSTRIDE (buf 0)
    float2* Hs1 = Hs0 + 64*HSTRIDE;                 // 64 x HSTRIDE (buf 1)

    int tid = threadIdx.x;
    int tm = tid >> 3;            // batch 0..63
    int tn = tid & 7;             // h-col within CTA's 8
    int base = blockIdx.x * 8, gc = base + tn;

    const float2* WE2 = (const float2*)WhhE;
    const float2* WD2 = (const float2*)WhhD;

    // load encoder Whh slice: rows r = gate(r>>3)*1024 + base + (r&7)
    for (int idx = tid; idx < 32*512; idx += 512){
        int r = idx >> 9, kk = idx & 511;
        int grow = ((r >> 3) << 10) + base + (r & 7);
        Ws2[r*WSTRIDE + kk] = WE2[(size_t)grow*512 + kk];
    }

    float cst = 0.f;              // cell state for (tm, gc), register-resident
    float* hA = g_hA;
    float* hB = g_hB;

    __syncthreads();

    for (int t = 0; t < 512; t++){
        int phase = t >> 8, tt = t & 255;
        if (t == 256){
            __syncthreads();
            for (int idx = tid; idx < 32*512; idx += 512){
                int r = idx >> 9, kk = idx & 511;
                int grow = ((r >> 3) << 10) + base + (r & 7);
                Ws2[r*WSTRIDE + kk] = WD2[(size_t)grow*512 + kk];
            }
            __syncthreads();
        }
        const float2* Hin2 = (const float2*)((t & 1) ? hB : hA);
        float* hout = (t & 1) ? hA : hB;
        const float* gxP = phase ? g_gx_dec : g_gx_enc;

        // prefetch gx gate quadruple (latency hidden under GEMM)
        float gxv[4];
        {
            const float* gxr = gxP + ((size_t)tm*Tt + tt)*G4;
            #pragma unroll
            for (int j=0;j<4;j++) gxv[j] = gxr[j*Hh + gc];
        }

        u64 acc[4];
        #pragma unroll
        for (int j=0;j<4;j++) acc[j] = 0ull;

        // tile 0: global -> smem buf0
        #pragma unroll
        for (int q=0;q<4;q++){
            int idx = tid + q*512, ml = idx >> 5, kp = idx & 31;
            Hs0[ml*HSTRIDE + kp] = Hin2[(size_t)ml*512 + kp];
        }
        __syncthreads();

        for (int kt = 0; kt < 16; kt++){
            float2* cur = (kt & 1) ? Hs1 : Hs0;
            float2* nxt = (kt & 1) ? Hs0 : Hs1;

            float2 pf[4];
            if (kt < 15){
                int kb = (kt+1)*32;
                #pragma unroll
                for (int q=0;q<4;q++){
                    int idx = tid + q*512, ml = idx >> 5, kp = idx & 31;
                    pf[q] = Hin2[(size_t)ml*512 + kb + kp];
                }
            }

            int kb0 = kt*32;
            #pragma unroll
            for (int kp2 = 0; kp2 < 16; kp2++){
                const u64* ap = (const u64*)&cur[tm*HSTRIDE + 2*kp2];
                u64 a0 = ap[0], a1 = ap[1];
                #pragma unroll
                for (int g = 0; g < 4; g++){
                    const u64* bp = (const u64*)&Ws2[(g*8 + tn)*WSTRIDE + kb0 + 2*kp2];
                    fma2(acc[g], a0, bp[0]);
                    fma2(acc[g], a1, bp[1]);
                }
            }

            if (kt < 15){
                #pragma unroll
                for (int q=0;q<4;q++){
                    int idx = tid + q*512, ml = idx >> 5, kp = idx & 31;
                    nxt[ml*HSTRIDE + kp] = pf[q];
                }
            }
            __syncthreads();
        }

        // fused LSTM pointwise (all in registers)
        {
            float iv = hsum(acc[0]) + gxv[0];
            float fv = hsum(acc[1]) + gxv[1];
            float gv = hsum(acc[2]) + gxv[2];
            float ov = hsum(acc[3]) + gxv[3];
            float si = 1.f / (1.f + expf(-iv));
            float sf = 1.f / (1.f + expf(-fv));
            float so = 1.f / (1.f + expf(-ov));
            cst = sf * cst + si * tanhf(gv);
            float h = so * tanhf(cst);
            hout[tm*Hh + gc] = h;
            if (phase)    g_hs[((size_t)tm*Tt + tt)*Hh + gc] = h;
            if (t == 255) lat[tm*Hh + gc] = h;
        }
        grid_bar();
    }
}

// ---- head: seq[m][n] = hs[m] . pred_W[n] + pred_b[n]   (unchanged; passed)
__global__ void k_head(const float* __restrict__ P, const float* __restrict__ pb,
                       float* __restrict__ seq){
    const float2* __restrict__ H2 = (const float2*)g_hs;
    const float2* __restrict__ P2 = (const float2*)P;

    __shared__ float2 As2[8*130];
    __shared__ float2 Bs2[8*66];

    int tid = threadIdx.x, tm = tid >> 4, tn = tid & 15;
    int m0 = blockIdx.y * 128, n0 = blockIdx.x * 64;

    u64 acc[8][4];
    #pragma unroll
    for (int i=0;i<8;i++)
        #pragma unroll
        for (int j=0;j<4;j++) acc[i][j] = 0ull;

    for (int kt = 0; kt < 64; kt++){
        int kb = kt * 8;
        #pragma unroll
        for (int q = 0; q < 4; q++){
            int idx = tid + q*256, ml = idx >> 3, kp = idx & 7;
            As2[kp*130 + ml] = H2[(size_t)(m0 + ml)*512 + kb + kp];
        }
        #pragma unroll
        for (int q = 0; q < 2; q++){
            int idx = tid + q*256, nl = idx >> 3, kp = idx & 7;
            int row = n0 + nl;
            float2 v = make_float2(0.f, 0.f);
            if (row < Dd) v = P2[(size_t)row*512 + kb + kp];
            Bs2[kp*66 + nl] = v;
        }
        __syncthreads();
        #pragma unroll
        for (int kp = 0; kp < 8; kp++){
            u64 a[8], b[4];
            #pragma unroll
            for (int i=0;i<8;i++) a[i] = *(const u64*)&As2[kp*130 + i*16 + tm];
            #pragma unroll
            for (int j=0;j<4;j++) b[j] = *(const u64*)&Bs2[kp*66 + j*16 + tn];
            #pragma unroll
            for (int i=0;i<8;i++)
                #pragma unroll
                for (int j=0;j<4;j++) fma2(acc[i][j], a[i], b[j]);
        }
        __syncthreads();
    }
    #pragma unroll
    for (int j=0;j<4;j++){
        int n = n0 + j*16 + tn;
        if (n >= Dd) continue;
        float bv = pb[n];
        #pragma unroll
        for (int i=0;i<8;i++)
            seq[(size_t)(m0 + i*16 + tm)*Dd + n] = hsum(acc[i][j]) + bv;
    }
}

static float* symaddr(const void* sym){
    void* p = 0;
    cudaGetSymbolAddress(&p, sym);
    return (float*)p;
}

extern "C" void kernel_launch(void* const* d_in, const int* in_sizes, int n_in,
                              void* d_out, int out_size) {
    const float* inputs  = (const float*)d_in[0];
    const float* enc_Wih = (const float*)d_in[1];
    const float* enc_Whh = (const float*)d_in[2];
    const float* enc_b   = (const float*)d_in[3];
    const float* dec_Wih = (const float*)d_in[4];
    const float* dec_Whh = (const float*)d_in[5];
    const float* dec_b   = (const float*)d_in[6];
    const float* pred_W  = (const float*)d_in[7];
    const float* pred_b  = (const float*)d_in[8];

    float* lat = (float*)d_out;               // [1,B,H]
    float* seq = (float*)d_out + Bb*Hh;       // [B,T,D]

    float* gxe = symaddr(g_gx_enc);
    float* gxd = symaddr(g_gx_dec);
    float* hA  = symaddr(g_hA);

    k_zero1<<<(Bb*Hh + 255)/256, 256>>>(hA, Bb*Hh);

    dim3 gg(G4/64, TB/128);
    k_gates<<<gg, 256>>>(inputs, enc_Wih, enc_b, gxe, 0);
    k_gates<<<gg, 256>>>(inputs, dec_Wih, dec_b, gxd, 1);

    // persistent recurrence: 128 CTAs (1/SM, smem-forced), 512 threads
    const int smem_bytes = (32*WSTRIDE + 2*64*HSTRIDE) * (int)sizeof(float2);  // 166,400
    cudaFuncSetAttribute(k_recur, cudaFuncAttributeMaxDynamicSharedMemorySize, smem_bytes);
    k_recur<<<NCTA, 512, smem_bytes>>>(enc_Whh, dec_Whh, lat);

    dim3 hg((Dd + 63)/64, TB/128);
    k_head<<<hg, 256>>>(pred_W, pred_b, seq);
}

// round 9
// speedup vs baseline: 3.2969x; 3.2969x over previous
#include <cuda_runtime.h>
#include <cuda_fp16.h>
#include <mma.h>
#include <stdint.h>
#include <math.h>

using namespace nvcuda;

#define Bb 64
#define Tt 256
#define Dd 409
#define Hh 1024
#define G4 4096
#define TB 16384   // B*T
#define NCTA 128
#define HLD 1032   // half lead dim (16B-aligned rows, conflict-free LDSM)

typedef unsigned long long u64;

__device__ float  g_gx_enc[(size_t)TB*G4];
__device__ float  g_gx_dec[(size_t)TB*G4];
__device__ float  g_hs[(size_t)TB*Hh];          // decoder h fp32 (head input)
__device__ __half g_h16[2][Bb*Hh];              // ping-pong h, fp16
__device__ unsigned g_cnt = 0;
__device__ unsigned g_gen = 0;

__device__ __forceinline__ void fma2(u64& d, u64 a, u64 b){
    asm("fma.rn.f32x2 %0, %1, %2, %0;" : "+l"(d) : "l"(a), "l"(b));
}
__device__ __forceinline__ float hsum(u64 v){
    float x, y;
    asm("mov.b64 {%0,%1}, %2;" : "=f"(x), "=f"(y) : "l"(v));
    return x + y;
}

__global__ void k_zero_h16(){
    int i = blockIdx.x*blockDim.x + threadIdx.x;
    if (i < Bb*Hh) g_h16[0][i] = __float2half_rn(0.f);
}

// ---- gates from x: gx[m][n] = x_row(m) . Wih[n] + bias[n]   (unchanged; passed)
__global__ void k_gates(const float* __restrict__ x, const float* __restrict__ W,
                        const float* __restrict__ bias, float* __restrict__ gx,
                        int shifted){
    __shared__ float Asf[8*260];
    __shared__ float Bsf[8*132];

    int tid = threadIdx.x, tm = tid >> 4, tn = tid & 15;
    int m0 = blockIdx.y * 128, n0 = blockIdx.x * 64;

    u64 acc[8][4];
    #pragma unroll
    for (int i=0;i<8;i++)
        #pragma unroll
        for (int j=0;j<4;j++) acc[i][j] = 0ull;

    for (int kt = 0; kt < 26; kt++){
        int k0 = kt * 16;
        #pragma unroll
        for (int q = 0; q < 8; q++){
            int idx = tid + q*256, ml = idx >> 4, kk = idx & 15;
            int k = k0 + kk, m = m0 + ml;
            float v = 0.f;
            if (k < Dd){
                if (!shifted)            v = x[(size_t)m*Dd + k];
                else if ((m & 255) != 0) v = x[(size_t)(m-1)*Dd + k];
            }
            Asf[(kk>>1)*260 + 2*ml + (kk&1)] = v;
        }
        #pragma unroll
        for (int q = 0; q < 4; q++){
            int idx = tid + q*256, nl = idx >> 4, kk = idx & 15;
            int k = k0 + kk;
            float v = (k < Dd) ? W[(size_t)(n0 + nl)*Dd + k] : 0.f;
            Bsf[(kk>>1)*132 + 2*nl + (kk&1)] = v;
        }
        __syncthreads();
        const u64* Au = (const u64*)Asf;
        const u64* Bu = (const u64*)Bsf;
        #pragma unroll
        for (int kp = 0; kp < 8; kp++){
            u64 a[8], b[4];
            #pragma unroll
            for (int i=0;i<8;i++) a[i] = Au[kp*130 + i*16 + tm];
            #pragma unroll
            for (int j=0;j<4;j++) b[j] = Bu[kp*66 + j*16 + tn];
            #pragma unroll
            for (int i=0;i<8;i++)
                #pragma unroll
                for (int j=0;j<4;j++) fma2(acc[i][j], a[i], b[j]);
        }
        __syncthreads();
    }
    #pragma unroll
    for (int j=0;j<4;j++){
        int n = n0 + j*16 + tn;
        float bv = bias[n];
        #pragma unroll
        for (int i=0;i<8;i++)
            gx[(size_t)(m0 + i*16 + tm)*G4 + n] = hsum(acc[i][j]) + bv;
    }
}

// ---- grid-wide generation barrier ----
__device__ __forceinline__ void grid_bar(){
    __threadfence();
    __syncthreads();
    if (threadIdx.x == 0){
        volatile unsigned* vgen = &g_gen;
        unsigned gen = *vgen;
        unsigned t = atomicAdd(&g_cnt, 1u);
        if (t == NCTA - 1){
            g_cnt = 0;
            __threadfence();
            *vgen = gen + 1;
        } else {
            while (*vgen == gen) { }
        }
        __threadfence();
    }
    __syncthreads();
}

// ---- persistent recurrence, tensor-core GEMM.
// 128 CTAs x 256 thr; CTA owns 8 h-cols (32 gate cols). Per step:
//   all-gather h (fp16, global) -> smem; G = h @ Whh_slice^T via wmma (fp32 acc);
//   fused fp32 LSTM pointwise, c register-resident; h out as fp16.
__global__ void __launch_bounds__(256, 1) k_recur(
    const float* __restrict__ WhhE, const float* __restrict__ WhhD,
    float* __restrict__ lat)
{
    extern __shared__ char smc[];
    __half* Hs = (__half*)smc;                         // 64 x HLD
    __half* Ws = (__half*)(smc + 64*HLD*2);            // 32 x HLD
    float*  Gs = (float* )(smc + (64+32)*HLD*2);       // 64 x 36

    int tid = threadIdx.x;
    int wid = tid >> 5;
    int wm = wid >> 1;            // 0..3  (m tile)
    int wn = wid & 1;             // 0..1  (n tile)
    int base = blockIdx.x * 8;

    // pointwise ownership: batch b = tid>>2, cols j0,j0+1 where j0=(tid&3)*2
    int pb_ = tid >> 2;
    int pj0 = (tid & 3) * 2;

    // load encoder Whh slice as fp16: row r -> gate(r>>3)*1024 + base + (r&7)
    for (int idx = tid; idx < 32*1024; idx += 256){
        int r = idx >> 10, k = idx & 1023;
        int grow = ((r >> 3) << 10) + base + (r & 7);
        Ws[r*HLD + k] = __float2half_rn(WhhE[(size_t)grow*1024 + k]);
    }

    float c0 = 0.f, c1 = 0.f;     // cell state, register-resident
    __syncthreads();

    for (int t = 0; t < 512; t++){
        int phase = t >> 8, tt = t & 255;
        if (t == 256){
            __syncthreads();
            for (int idx = tid; idx < 32*1024; idx += 256){
                int r = idx >> 10, k = idx & 1023;
                int grow = ((r >> 3) << 10) + base + (r & 7);
                Ws[r*HLD + k] = __float2half_rn(WhhD[(size_t)grow*1024 + k]);
            }
            __syncthreads();
        }
        const float* gxP = phase ? g_gx_dec : g_gx_enc;

        // prefetch gx gate quadruples for both owned cols (4 x LDG.64)
        float gxv[8];
        {
            const float* gxr = gxP + ((size_t)pb_*Tt + tt)*G4;
            #pragma unroll
            for (int g = 0; g < 4; g++){
                float2 v = *(const float2*)&gxr[g*1024 + base + pj0];
                gxv[2*g]   = v.x;
                gxv[2*g+1] = v.y;
            }
        }

        // all-gather h (fp16) -> smem
        {
            const uint4* src = (const uint4*)g_h16[t & 1];
            uint4* dst = (uint4*)Hs;
            #pragma unroll
            for (int q = 0; q < 32; q++){
                int idx = tid + q*256;            // 8192 uint4 = 64 x 128
                int row = idx >> 7, c8 = idx & 127;
                dst[row*129 + c8] = src[idx];     // HLD/8 = 129
            }
        }
        __syncthreads();

        // G[64x32] = Hs[64x1024] @ Ws[32x1024]^T  (wmma, fp32 accum)
        {
            wmma::fragment<wmma::accumulator,16,16,16,float> acc;
            wmma::fill_fragment(acc, 0.f);
            #pragma unroll 4
            for (int k = 0; k < 1024; k += 16){
                wmma::fragment<wmma::matrix_a,16,16,16,__half,wmma::row_major> af;
                wmma::fragment<wmma::matrix_b,16,16,16,__half,wmma::col_major> bf;
                wmma::load_matrix_sync(af, &Hs[(wm*16)*HLD + k], HLD);
                wmma::load_matrix_sync(bf, &Ws[(wn*16)*HLD + k], HLD);
                wmma::mma_sync(acc, af, bf, acc);
            }
            wmma::store_matrix_sync(&Gs[(wm*16)*36 + wn*16], acc, 36, wmma::mem_row_major);
        }
        __syncthreads();

        // fused LSTM pointwise (c in registers), write h fp16 for next step
        __half* hout = g_h16[(t + 1) & 1];
        #pragma unroll
        for (int p = 0; p < 2; p++){
            int j = pj0 + p;
            int gc = base + j;
            float iv = Gs[pb_*36 +      j] + gxv[0 + p];
            float fv = Gs[pb_*36 +  8 + j] + gxv[2 + p];
            float gv = Gs[pb_*36 + 16 + j] + gxv[4 + p];
            float ov = Gs[pb_*36 + 24 + j] + gxv[6 + p];
            float si = 1.f / (1.f + expf(-iv));
            float sf = 1.f / (1.f + expf(-fv));
            float so = 1.f / (1.f + expf(-ov));
            float cc = p ? c1 : c0;
            cc = sf * cc + si * tanhf(gv);
            float h = so * tanhf(cc);
            if (p) c1 = cc; else c0 = cc;
            hout[pb_*Hh + gc] = __float2half_rn(h);
            if (phase)    g_hs[((size_t)pb_*Tt + tt)*Hh + gc] = h;
            if (t == 255) lat[pb_*Hh + gc] = h;
        }
        grid_bar();
    }
}

// ---- head: seq[m][n] = hs[m] . pred_W[n] + pred_b[n]   (unchanged; passed)
__global__ void k_head(const float* __restrict__ P, const float* __restrict__ pb,
                       float* __restrict__ seq){
    const float2* __restrict__ H2 = (const float2*)g_hs;
    const float2* __restrict__ P2 = (const float2*)P;

    __shared__ float2 As2[8*130];
    __shared__ float2 Bs2[8*66];

    int tid = threadIdx.x, tm = tid >> 4, tn = tid & 15;
    int m0 = blockIdx.y * 128, n0 = blockIdx.x * 64;

    u64 acc[8][4];
    #pragma unroll
    for (int i=0;i<8;i++)
        #pragma unroll
        for (int j=0;j<4;j++) acc[i][j] = 0ull;

    for (int kt = 0; kt < 64; kt++){
        int kb = kt * 8;
        #pragma unroll
        for (int q = 0; q < 4; q++){
            int idx = tid + q*256, ml = idx >> 3, kp = idx & 7;
            As2[kp*130 + ml] = H2[(size_t)(m0 + ml)*512 + kb + kp];
        }
        #pragma unroll
        for (int q = 0; q < 2; q++){
            int idx = tid + q*256, nl = idx >> 3, kp = idx & 7;
            int row = n0 + nl;
            float2 v = make_float2(0.f, 0.f);
            if (row < Dd) v = P2[(size_t)row*512 + kb + kp];
            Bs2[kp*66 + nl] = v;
        }
        __syncthreads();
        #pragma unroll
        for (int kp = 0; kp < 8; kp++){
            u64 a[8], b[4];
            #pragma unroll
            for (int i=0;i<8;i++) a[i] = *(const u64*)&As2[kp*130 + i*16 + tm];
            #pragma unroll
            for (int j=0;j<4;j++) b[j] = *(const u64*)&Bs2[kp*66 + j*16 + tn];
            #pragma unroll
            for (int i=0;i<8;i++)
                #pragma unroll
                for (int j=0;j<4;j++) fma2(acc[i][j], a[i], b[j]);
        }
        __syncthreads();
    }
    #pragma unroll
    for (int j=0;j<4;j++){
        int n = n0 + j*16 + tn;
        if (n >= Dd) continue;
        float bv = pb[n];
        #pragma unroll
        for (int i=0;i<8;i++)
            seq[(size_t)(m0 + i*16 + tm)*Dd + n] = hsum(acc[i][j]) + bv;
    }
}

static float* symaddr(const void* sym){
    void* p = 0;
    cudaGetSymbolAddress(&p, sym);
    return (float*)p;
}

extern "C" void kernel_launch(void* const* d_in, const int* in_sizes, int n_in,
                              void* d_out, int out_size) {
    const float* inputs  = (const float*)d_in[0];
    const float* enc_Wih = (const float*)d_in[1];
    const float* enc_Whh = (const float*)d_in[2];
    const float* enc_b   = (const float*)d_in[3];
    const float* dec_Wih = (const float*)d_in[4];
    const float* dec_Whh = (const float*)d_in[5];
    const float* dec_b   = (const float*)d_in[6];
    const float* pred_W  = (const float*)d_in[7];
    const float* pred_b  = (const float*)d_in[8];

    float* lat = (float*)d_out;               // [1,B,H]
    float* seq = (float*)d_out + Bb*Hh;       // [B,T,D]

    float* gxe = symaddr(g_gx_enc);
    float* gxd = symaddr(g_gx_dec);

    k_zero_h16<<<(Bb*Hh + 255)/256, 256>>>();

    dim3 gg(G4/64, TB/128);
    k_gates<<<gg, 256>>>(inputs, enc_Wih, enc_b, gxe, 0);
    k_gates<<<gg, 256>>>(inputs, dec_Wih, dec_b, gxd, 1);

    // persistent tensor-core recurrence: 128 CTAs (1/SM, smem-forced), 256 thr
    const int smem_bytes = (64 + 32)*HLD*2 + 64*36*4;   // 207,360
    cudaFuncSetAttribute(k_recur, cudaFuncAttributeMaxDynamicSharedMemorySize, smem_bytes);
    k_recur<<<NCTA, 256, smem_bytes>>>(enc_Whh, dec_Whh, lat);

    dim3 hg((Dd + 63)/64, TB/128);
    k_head<<<hg, 256>>>(pred_W, pred_b, seq);
}

// round 10
// speedup vs baseline: 4.6809x; 1.4198x over previous
#include <cuda_runtime.h>
#include <cuda_fp16.h>
#include <mma.h>
#include <stdint.h>
#include <math.h>

using namespace nvcuda;

#define Bb 64
#define Tt 256
#define Dd 409
#define XP 416     // padded K for x/Wih
#define Hh 1024
#define G4 4096
#define TB 16384   // B*T
#define NCTA 128
#define HLD 1032   // half lead dim in recurrence smem

typedef unsigned long long u64;

__device__ float  g_gx_enc[(size_t)TB*G4];
__device__ float  g_gx_dec[(size_t)TB*G4];
__device__ float  g_hs[(size_t)TB*Hh];          // decoder h fp32 (head input)
__device__ __half g_h16[2][Bb*Hh];              // ping-pong h, fp16
__device__ __half g_x16[(size_t)TB*XP];         // x fp16, K padded
__device__ __half g_w16_enc[(size_t)G4*XP];     // enc_Wih fp16 padded
__device__ __half g_w16_dec[(size_t)G4*XP];     // dec_Wih fp16 padded
__device__ unsigned g_cnt = 0;
__device__ unsigned g_gen = 0;

__device__ __forceinline__ void fma2(u64& d, u64 a, u64 b){
    asm("fma.rn.f32x2 %0, %1, %2, %0;" : "+l"(d) : "l"(a), "l"(b));
}
__device__ __forceinline__ float hsum(u64 v){
    float x, y;
    asm("mov.b64 {%0,%1}, %2;" : "=f"(x), "=f"(y) : "l"(v));
    return x + y;
}

__global__ void k_zero_h16(){
    int i = blockIdx.x*blockDim.x + threadIdx.x;
    if (i < Bb*Hh) g_h16[0][i] = __float2half_rn(0.f);
}

// ---- conversions: pad K 409 -> 416, fp32 -> fp16 (row order preserved) ----
__global__ void k_conv_x16(const float* __restrict__ x){
    int i = blockIdx.x*blockDim.x + threadIdx.x;
    if (i >= TB*XP) return;
    int d = i % XP, m = i / XP;
    g_x16[i] = (d < Dd) ? __float2half_rn(x[(size_t)m*Dd + d]) : __float2half_rn(0.f);
}
__global__ void k_conv_w16(const float* __restrict__ w, __half* __restrict__ dst){
    int i = blockIdx.x*blockDim.x + threadIdx.x;
    if (i >= G4*XP) return;
    int d = i % XP, r = i / XP;
    dst[i] = (d < Dd) ? __float2half_rn(w[(size_t)r*Dd + d]) : __float2half_rn(0.f);
}

// ---- gates via WMMA: gx[m][n] = Xrow(m) . Wih[n] + bias[n]
// BM=128 x BN=64, BK=16, 256 thr (8 warps, 4x2, 32x32 each).
// shifted: A row m reads X16 row m-1, zero when t==0 (m%256==0).
__global__ void k_gates16(const __half* __restrict__ W16,
                          const float* __restrict__ bias,
                          float* __restrict__ gx, int shifted){
    __shared__ __align__(16) __half As[128*24];
    __shared__ __align__(16) __half Bs[64*24];
    __shared__ __align__(16) float  Cs[128*68];

    int tid = threadIdx.x, wid = tid >> 5;
    int m0 = blockIdx.y * 128, n0 = blockIdx.x * 64;
    int wm = (wid & 3) * 32, wn = (wid >> 2) * 32;

    wmma::fragment<wmma::accumulator,16,16,16,float> acc[2][2];
    #pragma unroll
    for (int i=0;i<2;i++)
        #pragma unroll
        for (int j=0;j<2;j++) wmma::fill_fragment(acc[i][j], 0.f);

    const uint32_t* Xu = (const uint32_t*)g_x16;
    const uint32_t* Wu = (const uint32_t*)W16;
    uint32_t* Asu = (uint32_t*)As;
    uint32_t* Bsu = (uint32_t*)Bs;

    for (int k0 = 0; k0 < XP; k0 += 16){
        int kp0 = k0 >> 1;
        #pragma unroll
        for (int q = 0; q < 4; q++){
            int idx = tid + q*256;          // 1024 u32 = 128 rows x 8
            int r = idx >> 3, kp = idx & 7;
            int m = m0 + r;
            uint32_t v = 0u;
            if (!shifted)            v = Xu[(size_t)m*208 + kp0 + kp];
            else if ((m & 255) != 0) v = Xu[(size_t)(m-1)*208 + kp0 + kp];
            Asu[r*12 + kp] = v;
        }
        #pragma unroll
        for (int q = 0; q < 2; q++){
            int idx = tid + q*256;          // 512 u32 = 64 rows x 8
            int nn = idx >> 3, kp = idx & 7;
            Bsu[nn*12 + kp] = Wu[(size_t)(n0 + nn)*208 + kp0 + kp];
        }
        __syncthreads();

        wmma::fragment<wmma::matrix_a,16,16,16,__half,wmma::row_major> af[2];
        wmma::fragment<wmma::matrix_b,16,16,16,__half,wmma::col_major> bf[2];
        wmma::load_matrix_sync(af[0], &As[(wm     )*24], 24);
        wmma::load_matrix_sync(af[1], &As[(wm + 16)*24], 24);
        wmma::load_matrix_sync(bf[0], &Bs[(wn     )*24], 24);
        wmma::load_matrix_sync(bf[1], &Bs[(wn + 16)*24], 24);
        #pragma unroll
        for (int i=0;i<2;i++)
            #pragma unroll
            for (int j=0;j<2;j++)
                wmma::mma_sync(acc[i][j], af[i], bf[j], acc[i][j]);
        __syncthreads();
    }

    wmma::store_matrix_sync(&Cs[(wm     )*68 + wn     ], acc[0][0], 68, wmma::mem_row_major);
    wmma::store_matrix_sync(&Cs[(wm     )*68 + wn + 16], acc[0][1], 68, wmma::mem_row_major);
    wmma::store_matrix_sync(&Cs[(wm + 16)*68 + wn     ], acc[1][0], 68, wmma::mem_row_major);
    wmma::store_matrix_sync(&Cs[(wm + 16)*68 + wn + 16], acc[1][1], 68, wmma::mem_row_major);
    __syncthreads();

    #pragma unroll
    for (int q = 0; q < 32; q++){
        int e = tid + q*256;               // 8192 = 128 x 64
        int r = e >> 6, cl = e & 63;
        int n = n0 + cl;
        gx[(size_t)(m0 + r)*G4 + n] = Cs[r*68 + cl] + bias[n];
    }
}

// ---- grid-wide generation barrier ----
__device__ __forceinline__ void grid_bar(){
    __threadfence();
    __syncthreads();
    if (threadIdx.x == 0){
        volatile unsigned* vgen = &g_gen;
        unsigned gen = *vgen;
        unsigned t = atomicAdd(&g_cnt, 1u);
        if (t == NCTA - 1){
            g_cnt = 0;
            __threadfence();
            *vgen = gen + 1;
        } else {
            while (*vgen == gen) { }
        }
        __threadfence();
    }
    __syncthreads();
}

// ---- persistent tensor-core recurrence (unchanged from R9; passed) ----
__global__ void __launch_bounds__(256, 1) k_recur(
    const float* __restrict__ WhhE, const float* __restrict__ WhhD,
    float* __restrict__ lat)
{
    extern __shared__ char smc[];
    __half* Hs = (__half*)smc;                         // 64 x HLD
    __half* Ws = (__half*)(smc + 64*HLD*2);            // 32 x HLD
    float*  Gs = (float* )(smc + (64+32)*HLD*2);       // 64 x 36

    int tid = threadIdx.x;
    int wid = tid >> 5;
    int wm = wid >> 1, wn = wid & 1;
    int base = blockIdx.x * 8;
    int pb_ = tid >> 2, pj0 = (tid & 3) * 2;

    for (int idx = tid; idx < 32*1024; idx += 256){
        int r = idx >> 10, k = idx & 1023;
        int grow = ((r >> 3) << 10) + base + (r & 7);
        Ws[r*HLD + k] = __float2half_rn(WhhE[(size_t)grow*1024 + k]);
    }

    float c0 = 0.f, c1 = 0.f;
    __syncthreads();

    for (int t = 0; t < 512; t++){
        int phase = t >> 8, tt = t & 255;
        if (t == 256){
            __syncthreads();
            for (int idx = tid; idx < 32*1024; idx += 256){
                int r = idx >> 10, k = idx & 1023;
                int grow = ((r >> 3) << 10) + base + (r & 7);
                Ws[r*HLD + k] = __float2half_rn(WhhD[(size_t)grow*1024 + k]);
            }
            __syncthreads();
        }
        const float* gxP = phase ? g_gx_dec : g_gx_enc;

        float gxv[8];
        {
            const float* gxr = gxP + ((size_t)pb_*Tt + tt)*G4;
            #pragma unroll
            for (int g = 0; g < 4; g++){
                float2 v = *(const float2*)&gxr[g*1024 + base + pj0];
                gxv[2*g]   = v.x;
                gxv[2*g+1] = v.y;
            }
        }

        {
            const uint4* src = (const uint4*)g_h16[t & 1];
            uint4* dst = (uint4*)Hs;
            #pragma unroll
            for (int q = 0; q < 32; q++){
                int idx = tid + q*256;
                int row = idx >> 7, c8 = idx & 127;
                dst[row*129 + c8] = src[idx];
            }
        }
        __syncthreads();

        {
            wmma::fragment<wmma::accumulator,16,16,16,float> acc;
            wmma::fill_fragment(acc, 0.f);
            #pragma unroll 4
            for (int k = 0; k < 1024; k += 16){
                wmma::fragment<wmma::matrix_a,16,16,16,__half,wmma::row_major> af;
                wmma::fragment<wmma::matrix_b,16,16,16,__half,wmma::col_major> bf;
                wmma::load_matrix_sync(af, &Hs[(wm*16)*HLD + k], HLD);
                wmma::load_matrix_sync(bf, &Ws[(wn*16)*HLD + k], HLD);
                wmma::mma_sync(acc, af, bf, acc);
            }
            wmma::store_matrix_sync(&Gs[(wm*16)*36 + wn*16], acc, 36, wmma::mem_row_major);
        }
        __syncthreads();

        __half* hout = g_h16[(t + 1) & 1];
        #pragma unroll
        for (int p = 0; p < 2; p++){
            int j = pj0 + p;
            int gc = base + j;
            float iv = Gs[pb_*36 +      j] + gxv[0 + p];
            float fv = Gs[pb_*36 +  8 + j] + gxv[2 + p];
            float gv = Gs[pb_*36 + 16 + j] + gxv[4 + p];
            float ov = Gs[pb_*36 + 24 + j] + gxv[6 + p];
            float si = 1.f / (1.f + expf(-iv));
            float sf = 1.f / (1.f + expf(-fv));
            float so = 1.f / (1.f + expf(-ov));
            float cc = p ? c1 : c0;
            cc = sf * cc + si * tanhf(gv);
            float h = so * tanhf(cc);
            if (p) c1 = cc; else c0 = cc;
            hout[pb_*Hh + gc] = __float2half_rn(h);
            if (phase)    g_hs[((size_t)pb_*Tt + tt)*Hh + gc] = h;
            if (t == 255) lat[pb_*Hh + gc] = h;
        }
        grid_bar();
    }
}

// ---- head: fp32 FFMA2 (unchanged; passed) ----
__global__ void k_head(const float* __restrict__ P, const float* __restrict__ pb,
                       float* __restrict__ seq){
    const float2* __restrict__ H2 = (const float2*)g_hs;
    const float2* __restrict__ P2 = (const float2*)P;

    __shared__ float2 As2[8*130];
    __shared__ float2 Bs2[8*66];

    int tid = threadIdx.x, tm = tid >> 4, tn = tid & 15;
    int m0 = blockIdx.y * 128, n0 = blockIdx.x * 64;

    u64 acc[8][4];
    #pragma unroll
    for (int i=0;i<8;i++)
        #pragma unroll
        for (int j=0;j<4;j++) acc[i][j] = 0ull;

    for (int kt = 0; kt < 64; kt++){
        int kb = kt * 8;
        #pragma unroll
        for (int q = 0; q < 4; q++){
            int idx = tid + q*256, ml = idx >> 3, kp = idx & 7;
            As2[kp*130 + ml] = H2[(size_t)(m0 + ml)*512 + kb + kp];
        }
        #pragma unroll
        for (int q = 0; q < 2; q++){
            int idx = tid + q*256, nl = idx >> 3, kp = idx & 7;
            int row = n0 + nl;
            float2 v = make_float2(0.f, 0.f);
            if (row < Dd) v = P2[(size_t)row*512 + kb + kp];
            Bs2[kp*66 + nl] = v;
        }
        __syncthreads();
        #pragma unroll
        for (int kp = 0; kp < 8; kp++){
            u64 a[8], b[4];
            #pragma unroll
            for (int i=0;i<8;i++) a[i] = *(const u64*)&As2[kp*130 + i*16 + tm];
            #pragma unroll
            for (int j=0;j<4;j++) b[j] = *(const u64*)&Bs2[kp*66 + j*16 + tn];
            #pragma unroll
            for (int i=0;i<8;i++)
                #pragma unroll
                for (int j=0;j<4;j++) fma2(acc[i][j], a[i], b[j]);
        }
        __syncthreads();
    }
    #pragma unroll
    for (int j=0;j<4;j++){
        int n = n0 + j*16 + tn;
        if (n >= Dd) continue;
        float bv = pb[n];
        #pragma unroll
        for (int i=0;i<8;i++)
            seq[(size_t)(m0 + i*16 + tm)*Dd + n] = hsum(acc[i][j]) + bv;
    }
}

static float* symaddr(const void* sym){
    void* p = 0;
    cudaGetSymbolAddress(&p, sym);
    return (float*)p;
}

extern "C" void kernel_launch(void* const* d_in, const int* in_sizes, int n_in,
                              void* d_out, int out_size) {
    const float* inputs  = (const float*)d_in[0];
    const float* enc_Wih = (const float*)d_in[1];
    const float* enc_Whh = (const float*)d_in[2];
    const float* enc_b   = (const float*)d_in[3];
    const float* dec_Wih = (const float*)d_in[4];
    const float* dec_Whh = (const float*)d_in[5];
    const float* dec_b   = (const float*)d_in[6];
    const float* pred_W  = (const float*)d_in[7];
    const float* pred_b  = (const float*)d_in[8];

    float* lat = (float*)d_out;               // [1,B,H]
    float* seq = (float*)d_out + Bb*Hh;       // [B,T,D]

    float* gxe = symaddr(g_gx_enc);
    float* gxd = symaddr(g_gx_dec);
    __half* w16e = (__half*)symaddr(g_w16_enc);
    __half* w16d = (__half*)symaddr(g_w16_dec);

    k_zero_h16<<<(Bb*Hh + 255)/256, 256>>>();
    k_conv_x16<<<(TB*XP + 255)/256, 256>>>(inputs);
    k_conv_w16<<<(G4*XP + 255)/256, 256>>>(enc_Wih, w16e);
    k_conv_w16<<<(G4*XP + 255)/256, 256>>>(dec_Wih, w16d);

    dim3 gg(G4/64, TB/128);
    k_gates16<<<gg, 256>>>(w16e, enc_b, gxe, 0);
    k_gates16<<<gg, 256>>>(w16d, dec_b, gxd, 1);

    const int smem_bytes = (64 + 32)*HLD*2 + 64*36*4;   // 207,360
    cudaFuncSetAttribute(k_recur, cudaFuncAttributeMaxDynamicSharedMemorySize, smem_bytes);
    k_recur<<<NCTA, 256, smem_bytes>>>(enc_Whh, dec_Whh, lat);

    dim3 hg((Dd + 63)/64, TB/128);
    k_head<<<hg, 256>>>(pred_W, pred_b, seq);
}

// round 11
// speedup vs baseline: 5.1302x; 1.0960x over previous
#include <cuda_runtime.h>
#include <cuda_fp16.h>
#include <mma.h>
#include <stdint.h>
#include <math.h>

using namespace nvcuda;

#define Bb 64
#define Tt 256
#define Dd 409
#define XP 416     // padded K for x/Wih
#define Hh 1024
#define G4 4096
#define TB 16384   // B*T
#define NCTA 128
#define HLD 1032   // half lead dim in recurrence smem

typedef unsigned long long u64;

__device__ float  g_gx_enc[(size_t)TB*G4];
__device__ float  g_gx_dec[(size_t)TB*G4];
__device__ float  g_hs[(size_t)TB*Hh];          // decoder h fp32 (head input)
__device__ __half g_h16[2][Bb*Hh];              // ping-pong h, fp16
__device__ __half g_x16[(size_t)TB*XP];         // x fp16, K padded
__device__ __half g_w16_enc[(size_t)G4*XP];     // enc_Wih fp16 padded
__device__ __half g_w16_dec[(size_t)G4*XP];     // dec_Wih fp16 padded
__device__ unsigned g_cnt = 0;
__device__ unsigned g_gen = 0;

__device__ __forceinline__ void fma2(u64& d, u64 a, u64 b){
    asm("fma.rn.f32x2 %0, %1, %2, %0;" : "+l"(d) : "l"(a), "l"(b));
}
__device__ __forceinline__ float hsum(u64 v){
    float x, y;
    asm("mov.b64 {%0,%1}, %2;" : "=f"(x), "=f"(y) : "l"(v));
    return x + y;
}

__global__ void k_zero_h16(){
    int i = blockIdx.x*blockDim.x + threadIdx.x;
    if (i < Bb*Hh) g_h16[0][i] = __float2half_rn(0.f);
}

// ---- conversions: pad K 409 -> 416, fp32 -> fp16 ----
__global__ void k_conv_x16(const float* __restrict__ x){
    int i = blockIdx.x*blockDim.x + threadIdx.x;
    if (i >= TB*XP) return;
    int d = i % XP, m = i / XP;
    g_x16[i] = (d < Dd) ? __float2half_rn(x[(size_t)m*Dd + d]) : __float2half_rn(0.f);
}
__global__ void k_conv_w16(const float* __restrict__ w, __half* __restrict__ dst){
    int i = blockIdx.x*blockDim.x + threadIdx.x;
    if (i >= G4*XP) return;
    int d = i % XP, r = i / XP;
    dst[i] = (d < Dd) ? __float2half_rn(w[(size_t)r*Dd + d]) : __float2half_rn(0.f);
}

// ---- gates via WMMA v2: BK=32, double-buffered, register-staged prefetch.
// gx[m][n] = Xrow(m).Wih[n] + bias[n]; BM=128 BN=64; 256 thr (8 warps 4x2).
// 13 k-iters of 32 (13*32 = 416 = XP). Epilogue Cs aliases A/B buffers.
__global__ void k_gates16(const __half* __restrict__ W16,
                          const float* __restrict__ bias,
                          float* __restrict__ gx, int shifted){
    extern __shared__ char dsm[];
    __half* As[2] = { (__half*)dsm,              (__half*)(dsm + 10240) };
    __half* Bs[2] = { (__half*)(dsm + 20480),    (__half*)(dsm + 25600) };
    float*  Cs    = (float*)dsm;                  // aliases (used after loop)

    int tid = threadIdx.x, wid = tid >> 5;
    int m0 = blockIdx.y * 128, n0 = blockIdx.x * 64;
    int wm = (wid & 3) * 32, wn = (wid >> 2) * 32;

    wmma::fragment<wmma::accumulator,16,16,16,float> acc[2][2];
    #pragma unroll
    for (int i=0;i<2;i++)
        #pragma unroll
        for (int j=0;j<2;j++) wmma::fill_fragment(acc[i][j], 0.f);

    const uint32_t* Xu = (const uint32_t*)g_x16;
    const uint32_t* Wu = (const uint32_t*)W16;

    // load tile kt=0 into buf 0
    {
        uint32_t* Au = (uint32_t*)As[0];
        uint32_t* Bu = (uint32_t*)Bs[0];
        #pragma unroll
        for (int q = 0; q < 8; q++){
            int idx = tid + q*256, r = idx >> 4, kp = idx & 15;
            int m = m0 + r;
            uint32_t v = 0u;
            if (!shifted)            v = Xu[(size_t)m*208 + kp];
            else if ((m & 255) != 0) v = Xu[(size_t)(m-1)*208 + kp];
            Au[r*20 + kp] = v;
        }
        #pragma unroll
        for (int q = 0; q < 4; q++){
            int idx = tid + q*256, r = idx >> 4, kp = idx & 15;
            Bu[r*20 + kp] = Wu[(size_t)(n0 + r)*208 + kp];
        }
    }
    __syncthreads();

    for (int kt = 0; kt < 13; kt++){
        int cur = kt & 1, nxt = cur ^ 1;

        // register-stage next tile (overlaps with compute below)
        uint32_t pfa[8], pfb[4];
        if (kt < 12){
            int kb = (kt+1)*16;
            #pragma unroll
            for (int q = 0; q < 8; q++){
                int idx = tid + q*256, r = idx >> 4, kp = idx & 15;
                int m = m0 + r;
                uint32_t v = 0u;
                if (!shifted)            v = Xu[(size_t)m*208 + kb + kp];
                else if ((m & 255) != 0) v = Xu[(size_t)(m-1)*208 + kb + kp];
                pfa[q] = v;
            }
            #pragma unroll
            for (int q = 0; q < 4; q++){
                int idx = tid + q*256, r = idx >> 4, kp = idx & 15;
                pfb[q] = Wu[(size_t)(n0 + r)*208 + kb + kp];
            }
        }

        // compute current tile: 2 sub-k of 16
        #pragma unroll
        for (int sub = 0; sub < 2; sub++){
            wmma::fragment<wmma::matrix_a,16,16,16,__half,wmma::row_major> af[2];
            wmma::fragment<wmma::matrix_b,16,16,16,__half,wmma::col_major> bf[2];
            wmma::load_matrix_sync(af[0], &As[cur][(wm     )*40 + sub*16], 40);
            wmma::load_matrix_sync(af[1], &As[cur][(wm + 16)*40 + sub*16], 40);
            wmma::load_matrix_sync(bf[0], &Bs[cur][(wn     )*40 + sub*16], 40);
            wmma::load_matrix_sync(bf[1], &Bs[cur][(wn + 16)*40 + sub*16], 40);
            #pragma unroll
            for (int i=0;i<2;i++)
                #pragma unroll
                for (int j=0;j<2;j++)
                    wmma::mma_sync(acc[i][j], af[i], bf[j], acc[i][j]);
        }

        if (kt < 12){
            uint32_t* Au = (uint32_t*)As[nxt];
            uint32_t* Bu = (uint32_t*)Bs[nxt];
            #pragma unroll
            for (int q = 0; q < 8; q++){
                int idx = tid + q*256, r = idx >> 4, kp = idx & 15;
                Au[r*20 + kp] = pfa[q];
            }
            #pragma unroll
            for (int q = 0; q < 4; q++){
                int idx = tid + q*256, r = idx >> 4, kp = idx & 15;
                Bu[r*20 + kp] = pfb[q];
            }
        }
        __syncthreads();
    }

    // epilogue (Cs aliases the A/B buffers; loop-exit sync above protects it)
    wmma::store_matrix_sync(&Cs[(wm     )*68 + wn     ], acc[0][0], 68, wmma::mem_row_major);
    wmma::store_matrix_sync(&Cs[(wm     )*68 + wn + 16], acc[0][1], 68, wmma::mem_row_major);
    wmma::store_matrix_sync(&Cs[(wm + 16)*68 + wn     ], acc[1][0], 68, wmma::mem_row_major);
    wmma::store_matrix_sync(&Cs[(wm + 16)*68 + wn + 16], acc[1][1], 68, wmma::mem_row_major);
    __syncthreads();

    #pragma unroll
    for (int q = 0; q < 32; q++){
        int e = tid + q*256;               // 8192 = 128 x 64
        int r = e >> 6, cl = e & 63;
        int n = n0 + cl;
        gx[(size_t)(m0 + r)*G4 + n] = Cs[r*68 + cl] + bias[n];
    }
}

// ---- grid-wide generation barrier ----
__device__ __forceinline__ void grid_bar(){
    __threadfence();
    __syncthreads();
    if (threadIdx.x == 0){
        volatile unsigned* vgen = &g_gen;
        unsigned gen = *vgen;
        unsigned t = atomicAdd(&g_cnt, 1u);
        if (t == NCTA - 1){
            g_cnt = 0;
            __threadfence();
            *vgen = gen + 1;
        } else {
            while (*vgen == gen) { }
        }
        __threadfence();
    }
    __syncthreads();
}

// ---- persistent tensor-core recurrence v2: CTA owns (batch-half x 16 h-cols).
// 128 CTAs x 256 thr: s = bx&1 (32 batches), cb = bx>>1 (cols base cb*16).
// Gather = 32x1024 fp16 (64KB) per step. G[32x64] = Hs @ Ws^T, 8 warps 2x4.
__global__ void __launch_bounds__(256, 1) k_recur(
    const float* __restrict__ WhhE, const float* __restrict__ WhhD,
    float* __restrict__ lat)
{
    extern __shared__ char smc[];
    __half* Ws = (__half*)smc;                          // 64 x HLD
    __half* Hs = (__half*)(smc + 64*HLD*2);             // 32 x HLD
    float*  Gs = (float* )(smc + (64+32)*HLD*2);        // 32 x 68

    int tid = threadIdx.x;
    int wid = tid >> 5;
    int wm = wid >> 2;            // 0..1  (batch tile)
    int wn = wid & 3;             // 0..3  (gate-col tile)
    int s    = blockIdx.x & 1;          // batch half
    int cb   = blockIdx.x >> 1;         // col block
    int base = cb * 16;
    int boff = s * 32;                  // batch offset

    int pb_ = tid >> 3;                 // 0..31 local batch
    int pj0 = (tid & 7) * 2;            // col pair 0..14

    // load encoder Whh slice: row r -> gate(r>>4)*1024 + base + (r&15)
    for (int idx = tid; idx < 64*1024; idx += 256){
        int r = idx >> 10, k = idx & 1023;
        int grow = ((r >> 4) << 10) + base + (r & 15);
        Ws[r*HLD + k] = __float2half_rn(WhhE[(size_t)grow*1024 + k]);
    }

    float c0 = 0.f, c1 = 0.f;
    __syncthreads();

    for (int t = 0; t < 512; t++){
        int phase = t >> 8, tt = t & 255;
        if (t == 256){
            __syncthreads();
            for (int idx = tid; idx < 64*1024; idx += 256){
                int r = idx >> 10, k = idx & 1023;
                int grow = ((r >> 4) << 10) + base + (r & 15);
                Ws[r*HLD + k] = __float2half_rn(WhhD[(size_t)grow*1024 + k]);
            }
            __syncthreads();
        }
        const float* gxP = phase ? g_gx_dec : g_gx_enc;

        // prefetch gx gate quadruples for both owned cols
        float gxv[8];
        {
            const float* gxr = gxP + ((size_t)(boff + pb_)*Tt + tt)*G4;
            #pragma unroll
            for (int g = 0; g < 4; g++){
                float2 v = *(const float2*)&gxr[g*1024 + base + pj0];
                gxv[2*g]   = v.x;
                gxv[2*g+1] = v.y;
            }
        }

        // gather this CTA's 32 batch rows of h (fp16) -> smem
        {
            const uint4* src = (const uint4*)g_h16[t & 1];
            uint4* dst = (uint4*)Hs;
            #pragma unroll
            for (int q = 0; q < 16; q++){
                int idx = tid + q*256;              // 4096 uint4 = 32 x 128
                int row = idx >> 7, c8 = idx & 127;
                dst[row*129 + c8] = src[(size_t)(boff + row)*128 + c8];
            }
        }
        __syncthreads();

        // G[32x64] = Hs[32x1024] @ Ws[64x1024]^T  (each warp one 16x16)
        {
            wmma::fragment<wmma::accumulator,16,16,16,float> acc;
            wmma::fill_fragment(acc, 0.f);
            #pragma unroll 4
            for (int k = 0; k < 1024; k += 16){
                wmma::fragment<wmma::matrix_a,16,16,16,__half,wmma::row_major> af;
                wmma::fragment<wmma::matrix_b,16,16,16,__half,wmma::col_major> bf;
                wmma::load_matrix_sync(af, &Hs[(wm*16)*HLD + k], HLD);
                wmma::load_matrix_sync(bf, &Ws[(wn*16)*HLD + k], HLD);
                wmma::mma_sync(acc, af, bf, acc);
            }
            wmma::store_matrix_sync(&Gs[(wm*16)*68 + wn*16], acc, 68, wmma::mem_row_major);
        }
        __syncthreads();

        // fused LSTM pointwise (c in registers), write h fp16 for next step
        __half* hout = g_h16[(t + 1) & 1];
        #pragma unroll
        for (int p = 0; p < 2; p++){
            int j = pj0 + p;
            int gc = base + j;
            int b  = boff + pb_;
            float iv = Gs[pb_*68 +      j] + gxv[0 + p];
            float fv = Gs[pb_*68 + 16 + j] + gxv[2 + p];
            float gv = Gs[pb_*68 + 32 + j] + gxv[4 + p];
            float ov = Gs[pb_*68 + 48 + j] + gxv[6 + p];
            float si = 1.f / (1.f + expf(-iv));
            float sf = 1.f / (1.f + expf(-fv));
            float so = 1.f / (1.f + expf(-ov));
            float cc = p ? c1 : c0;
            cc = sf * cc + si * tanhf(gv);
            float h = so * tanhf(cc);
            if (p) c1 = cc; else c0 = cc;
            hout[b*Hh + gc] = __float2half_rn(h);
            if (phase)    g_hs[((size_t)b*Tt + tt)*Hh + gc] = h;
            if (t == 255) lat[b*Hh + gc] = h;
        }
        grid_bar();
    }
}

// ---- head: fp32 FFMA2 (unchanged; passed) ----
__global__ void k_head(const float* __restrict__ P, const float* __restrict__ pb,
                       float* __restrict__ seq){
    const float2* __restrict__ H2 = (const float2*)g_hs;
    const float2* __restrict__ P2 = (const float2*)P;

    __shared__ float2 As2[8*130];
    __shared__ float2 Bs2[8*66];

    int tid = threadIdx.x, tm = tid >> 4, tn = tid & 15;
    int m0 = blockIdx.y * 128, n0 = blockIdx.x * 64;

    u64 acc[8][4];
    #pragma unroll
    for (int i=0;i<8;i++)
        #pragma unroll
        for (int j=0;j<4;j++) acc[i][j] = 0ull;

    for (int kt = 0; kt < 64; kt++){
        int kb = kt * 8;
        #pragma unroll
        for (int q = 0; q < 4; q++){
            int idx = tid + q*256, ml = idx >> 3, kp = idx & 7;
            As2[kp*130 + ml] = H2[(size_t)(m0 + ml)*512 + kb + kp];
        }
        #pragma unroll
        for (int q = 0; q < 2; q++){
            int idx = tid + q*256, nl = idx >> 3, kp = idx & 7;
            int row = n0 + nl;
            float2 v = make_float2(0.f, 0.f);
            if (row < Dd) v = P2[(size_t)row*512 + kb + kp];
            Bs2[kp*66 + nl] = v;
        }
        __syncthreads();
        #pragma unroll
        for (int kp = 0; kp < 8; kp++){
            u64 a[8], b[4];
            #pragma unroll
            for (int i=0;i<8;i++) a[i] = *(const u64*)&As2[kp*130 + i*16 + tm];
            #pragma unroll
            for (int j=0;j<4;j++) b[j] = *(const u64*)&Bs2[kp*66 + j*16 + tn];
            #pragma unroll
            for (int i=0;i<8;i++)
                #pragma unroll
                for (int j=0;j<4;j++) fma2(acc[i][j], a[i], b[j]);
        }
        __syncthreads();
    }
    #pragma unroll
    for (int j=0;j<4;j++){
        int n = n0 + j*16 + tn;
        if (n >= Dd) continue;
        float bv = pb[n];
        #pragma unroll
        for (int i=0;i<8;i++)
            seq[(size_t)(m0 + i*16 + tm)*Dd + n] = hsum(acc[i][j]) + bv;
    }
}

static float* symaddr(const void* sym){
    void* p = 0;
    cudaGetSymbolAddress(&p, sym);
    return (float*)p;
}

extern "C" void kernel_launch(void* const* d_in, const int* in_sizes, int n_in,
                              void* d_out, int out_size) {
    const float* inputs  = (const float*)d_in[0];
    const float* enc_Wih = (const float*)d_in[1];
    const float* enc_Whh = (const float*)d_in[2];
    const float* enc_b   = (const float*)d_in[3];
    const float* dec_Wih = (const float*)d_in[4];
    const float* dec_Whh = (const float*)d_in[5];
    const float* dec_b   = (const float*)d_in[6];
    const float* pred_W  = (const float*)d_in[7];
    const float* pred_b  = (const float*)d_in[8];

    float* lat = (float*)d_out;               // [1,B,H]
    float* seq = (float*)d_out + Bb*Hh;       // [B,T,D]

    float* gxe = symaddr(g_gx_enc);
    float* gxd = symaddr(g_gx_dec);
    __half* w16e = (__half*)symaddr(g_w16_enc);
    __half* w16d = (__half*)symaddr(g_w16_dec);

    k_zero_h16<<<(Bb*Hh + 255)/256, 256>>>();
    k_conv_x16<<<(TB*XP + 255)/256, 256>>>(inputs);
    k_conv_w16<<<(G4*XP + 255)/256, 256>>>(enc_Wih, w16e);
    k_conv_w16<<<(G4*XP + 255)/256, 256>>>(dec_Wih, w16d);

    // gates: dynamic smem = max(A/B buffers 30720B, Cs 34816B) = 34816B
    const int gsmem = 35840;
    dim3 gg(G4/64, TB/128);
    k_gates16<<<gg, 256, gsmem>>>(w16e, enc_b, gxe, 0);
    k_gates16<<<gg, 256, gsmem>>>(w16d, dec_b, gxd, 1);

    // recurrence: Ws 64xHLD + Hs 32xHLD (fp16) + Gs 32x68 (fp32) = 206,848B
    const int rsmem = (64 + 32)*HLD*2 + 32*68*4;
    cudaFuncSetAttribute(k_recur, cudaFuncAttributeMaxDynamicSharedMemorySize, rsmem);
    k_recur<<<NCTA, 256, rsmem>>>(enc_Whh, dec_Whh, lat);

    dim3 hg((Dd + 63)/64, TB/128);
    k_head<<<hg, 256>>>(pred_W, pred_b, seq);
}

// round 12
// speedup vs baseline: 6.3287x; 1.2336x over previous
#include <cuda_runtime.h>
#include <cuda_fp16.h>
#include <mma.h>
#include <stdint.h>
#include <math.h>

using namespace nvcuda;

#define Bb 64
#define Tt 256
#define Dd 409
#define XP 416     // padded K for x/Wih
#define Hh 1024
#define G4 4096
#define TB 16384   // B*T
#define NCTA 128
#define HLD 1032   // half lead dim in recurrence smem

__device__ float  g_gx_enc[(size_t)TB*G4];
__device__ float  g_gx_dec[(size_t)TB*G4];
__device__ __half g_hs16[(size_t)TB*Hh];        // decoder h fp16 (head input)
__device__ __half g_h16[2][Bb*Hh];              // ping-pong h, fp16
__device__ __half g_x16[(size_t)TB*XP];         // x fp16, K padded
__device__ __half g_w16_enc[(size_t)G4*XP];     // enc_Wih fp16 padded
__device__ __half g_w16_dec[(size_t)G4*XP];     // dec_Wih fp16 padded
__device__ __half g_pw16[(size_t)448*Hh];       // pred_W fp16, rows padded 409->448
__device__ unsigned g_pflag[2][64];             // producer step counters (per half)
__device__ unsigned g_cflag[2][64];             // consumer-ack step counters

__global__ void k_init(){
    int i = blockIdx.x*blockDim.x + threadIdx.x;
    if (i < Bb*Hh) g_h16[0][i] = __float2half_rn(0.f);
    if (blockIdx.x == 0 && threadIdx.x < 128){
        int s = threadIdx.x >> 6, c = threadIdx.x & 63;
        g_pflag[s][c] = 0u;
        g_cflag[s][c] = 0u;
    }
}

// ---- conversions: fp32 -> fp16 with padding ----
__global__ void k_conv_x16(const float* __restrict__ x){
    int i = blockIdx.x*blockDim.x + threadIdx.x;
    if (i >= TB*XP) return;
    int d = i % XP, m = i / XP;
    g_x16[i] = (d < Dd) ? __float2half_rn(x[(size_t)m*Dd + d]) : __float2half_rn(0.f);
}
__global__ void k_conv_w16(const float* __restrict__ w, __half* __restrict__ dst){
    int i = blockIdx.x*blockDim.x + threadIdx.x;
    if (i >= G4*XP) return;
    int d = i % XP, r = i / XP;
    dst[i] = (d < Dd) ? __float2half_rn(w[(size_t)r*Dd + d]) : __float2half_rn(0.f);
}
__global__ void k_conv_pw16(const float* __restrict__ w){
    int i = blockIdx.x*blockDim.x + threadIdx.x;
    if (i >= 448*Hh) return;
    int r = i >> 10;
    g_pw16[i] = (r < Dd) ? __float2half_rn(w[i]) : __float2half_rn(0.f);
}

// ---- gates via WMMA (unchanged from R11; passed): BK=32, double-buffered ----
__global__ void k_gates16(const __half* __restrict__ W16,
                          const float* __restrict__ bias,
                          float* __restrict__ gx, int shifted){
    extern __shared__ char dsm[];
    __half* As[2] = { (__half*)dsm,              (__half*)(dsm + 10240) };
    __half* Bs[2] = { (__half*)(dsm + 20480),    (__half*)(dsm + 25600) };
    float*  Cs    = (float*)dsm;

    int tid = threadIdx.x, wid = tid >> 5;
    int m0 = blockIdx.y * 128, n0 = blockIdx.x * 64;
    int wm = (wid & 3) * 32, wn = (wid >> 2) * 32;

    wmma::fragment<wmma::accumulator,16,16,16,float> acc[2][2];
    #pragma unroll
    for (int i=0;i<2;i++)
        #pragma unroll
        for (int j=0;j<2;j++) wmma::fill_fragment(acc[i][j], 0.f);

    const uint32_t* Xu = (const uint32_t*)g_x16;
    const uint32_t* Wu = (const uint32_t*)W16;

    {
        uint32_t* Au = (uint32_t*)As[0];
        uint32_t* Bu = (uint32_t*)Bs[0];
        #pragma unroll
        for (int q = 0; q < 8; q++){
            int idx = tid + q*256, r = idx >> 4, kp = idx & 15;
            int m = m0 + r;
            uint32_t v = 0u;
            if (!shifted)            v = Xu[(size_t)m*208 + kp];
            else if ((m & 255) != 0) v = Xu[(size_t)(m-1)*208 + kp];
            Au[r*20 + kp] = v;
        }
        #pragma unroll
        for (int q = 0; q < 4; q++){
            int idx = tid + q*256, r = idx >> 4, kp = idx & 15;
            Bu[r*20 + kp] = Wu[(size_t)(n0 + r)*208 + kp];
        }
    }
    __syncthreads();

    for (int kt = 0; kt < 13; kt++){
        int cur = kt & 1, nxt = cur ^ 1;
        uint32_t pfa[8], pfb[4];
        if (kt < 12){
            int kb = (kt+1)*16;
            #pragma unroll
            for (int q = 0; q < 8; q++){
                int idx = tid + q*256, r = idx >> 4, kp = idx & 15;
                int m = m0 + r;
                uint32_t v = 0u;
                if (!shifted)            v = Xu[(size_t)m*208 + kb + kp];
                else if ((m & 255) != 0) v = Xu[(size_t)(m-1)*208 + kb + kp];
                pfa[q] = v;
            }
            #pragma unroll
            for (int q = 0; q < 4; q++){
                int idx = tid + q*256, r = idx >> 4, kp = idx & 15;
                pfb[q] = Wu[(size_t)(n0 + r)*208 + kb + kp];
            }
        }
        #pragma unroll
        for (int sub = 0; sub < 2; sub++){
            wmma::fragment<wmma::matrix_a,16,16,16,__half,wmma::row_major> af[2];
            wmma::fragment<wmma::matrix_b,16,16,16,__half,wmma::col_major> bf[2];
            wmma::load_matrix_sync(af[0], &As[cur][(wm     )*40 + sub*16], 40);
            wmma::load_matrix_sync(af[1], &As[cur][(wm + 16)*40 + sub*16], 40);
            wmma::load_matrix_sync(bf[0], &Bs[cur][(wn     )*40 + sub*16], 40);
            wmma::load_matrix_sync(bf[1], &Bs[cur][(wn + 16)*40 + sub*16], 40);
            #pragma unroll
            for (int i=0;i<2;i++)
                #pragma unroll
                for (int j=0;j<2;j++)
                    wmma::mma_sync(acc[i][j], af[i], bf[j], acc[i][j]);
        }
        if (kt < 12){
            uint32_t* Au = (uint32_t*)As[nxt];
            uint32_t* Bu = (uint32_t*)Bs[nxt];
            #pragma unroll
            for (int q = 0; q < 8; q++){
                int idx = tid + q*256, r = idx >> 4, kp = idx & 15;
                Au[r*20 + kp] = pfa[q];
            }
            #pragma unroll
            for (int q = 0; q < 4; q++){
                int idx = tid + q*256, r = idx >> 4, kp = idx & 15;
                Bu[r*20 + kp] = pfb[q];
            }
        }
        __syncthreads();
    }

    wmma::store_matrix_sync(&Cs[(wm     )*68 + wn     ], acc[0][0], 68, wmma::mem_row_major);
    wmma::store_matrix_sync(&Cs[(wm     )*68 + wn + 16], acc[0][1], 68, wmma::mem_row_major);
    wmma::store_matrix_sync(&Cs[(wm + 16)*68 + wn     ], acc[1][0], 68, wmma::mem_row_major);
    wmma::store_matrix_sync(&Cs[(wm + 16)*68 + wn + 16], acc[1][1], 68, wmma::mem_row_major);
    __syncthreads();

    #pragma unroll
    for (int q = 0; q < 32; q++){
        int e = tid + q*256;
        int r = e >> 6, cl = e & 63;
        int n = n0 + cl;
        gx[(size_t)(m0 + r)*G4 + n] = Cs[r*68 + cl] + bias[n];
    }
}

// ---- persistent recurrence v3: distributed flag handshake (two independent
// 64-CTA halves), __ldcg gather, backward-ack off the critical path. ----
__global__ void __launch_bounds__(256, 1) k_recur(
    const float* __restrict__ WhhE, const float* __restrict__ WhhD,
    float* __restrict__ lat)
{
    extern __shared__ char smc[];
    __half* Ws = (__half*)smc;                          // 64 x HLD
    __half* Hs = (__half*)(smc + 64*HLD*2);             // 32 x HLD
    float*  Gs = (float* )(smc + (64+32)*HLD*2);        // 32 x 68

    int tid = threadIdx.x;
    int wid = tid >> 5;
    int wm = wid >> 2, wn = wid & 3;
    int s    = blockIdx.x & 1;          // batch half
    int cb   = blockIdx.x >> 1;         // col block (0..63)
    int base = cb * 16;
    int boff = s * 32;

    int pb_ = tid >> 3;                 // 0..31 local batch
    int pj0 = (tid & 7) * 2;            // col pair

    volatile unsigned* pf = g_pflag[s];
    volatile unsigned* cf = g_cflag[s];

    for (int idx = tid; idx < 64*1024; idx += 256){
        int r = idx >> 10, k = idx & 1023;
        int grow = ((r >> 4) << 10) + base + (r & 15);
        Ws[r*HLD + k] = __float2half_rn(WhhE[(size_t)grow*1024 + k]);
    }

    float c0 = 0.f, c1 = 0.f;
    __syncthreads();

    for (int t = 0; t < 512; t++){
        int phase = t >> 8, tt = t & 255;
        if (t == 256){
            __syncthreads();
            for (int idx = tid; idx < 64*1024; idx += 256){
                int r = idx >> 10, k = idx & 1023;
                int grow = ((r >> 4) << 10) + base + (r & 15);
                Ws[r*HLD + k] = __float2half_rn(WhhD[(size_t)grow*1024 + k]);
            }
            __syncthreads();
        }
        const float* gxP = phase ? g_gx_dec : g_gx_enc;

        // forward wait: producers of my half published h for step t
        if (t > 0){
            if (tid < 64){ while (pf[tid] < (unsigned)t) { } }
            __syncthreads();
        }

        // prefetch gx gate quadruples
        float gxv[8];
        {
            const float* gxr = gxP + ((size_t)(boff + pb_)*Tt + tt)*G4;
            #pragma unroll
            for (int g = 0; g < 4; g++){
                float2 v = *(const float2*)&gxr[g*1024 + base + pj0];
                gxv[2*g]   = v.x;
                gxv[2*g+1] = v.y;
            }
        }

        // gather 32 batch rows of h (fp16) -> smem, L1-bypassing
        {
            const uint4* src = (const uint4*)g_h16[t & 1];
            uint4* dst = (uint4*)Hs;
            #pragma unroll
            for (int q = 0; q < 16; q++){
                int idx = tid + q*256;
                int row = idx >> 7, c8 = idx & 127;
                dst[row*129 + c8] = __ldcg(&src[(size_t)(boff + row)*128 + c8]);
            }
        }
        __syncthreads();
        if (tid == 0) atomicExch((unsigned*)&cf[cb], (unsigned)(t + 1));  // ack read of buf t&1

        // G[32x64] = Hs @ Ws^T
        {
            wmma::fragment<wmma::accumulator,16,16,16,float> acc;
            wmma::fill_fragment(acc, 0.f);
            #pragma unroll 4
            for (int k = 0; k < 1024; k += 16){
                wmma::fragment<wmma::matrix_a,16,16,16,__half,wmma::row_major> af;
                wmma::fragment<wmma::matrix_b,16,16,16,__half,wmma::col_major> bf;
                wmma::load_matrix_sync(af, &Hs[(wm*16)*HLD + k], HLD);
                wmma::load_matrix_sync(bf, &Ws[(wn*16)*HLD + k], HLD);
                wmma::mma_sync(acc, af, bf, acc);
            }
            wmma::store_matrix_sync(&Gs[(wm*16)*68 + wn*16], acc, 68, wmma::mem_row_major);
        }
        __syncthreads();

        // pointwise into registers
        int b = boff + pb_;
        float hv[2];
        #pragma unroll
        for (int p = 0; p < 2; p++){
            int j = pj0 + p;
            float iv = Gs[pb_*68 +      j] + gxv[0 + p];
            float fv = Gs[pb_*68 + 16 + j] + gxv[2 + p];
            float gv = Gs[pb_*68 + 32 + j] + gxv[4 + p];
            float ov = Gs[pb_*68 + 48 + j] + gxv[6 + p];
            float si = 1.f / (1.f + expf(-iv));
            float sf = 1.f / (1.f + expf(-fv));
            float so = 1.f / (1.f + expf(-ov));
            float cc = p ? c1 : c0;
            cc = sf * cc + si * tanhf(gv);
            hv[p] = so * tanhf(cc);
            if (p) c1 = cc; else c0 = cc;
        }

        // backward wait: all consumers done reading the buffer I'm about to write
        if (t > 0){
            if (tid < 64){ while (cf[tid] < (unsigned)t) { } }
            __syncthreads();
        }

        // stores
        __half2 hh = __floats2half2_rn(hv[0], hv[1]);
        *(__half2*)&g_h16[(t + 1) & 1][b*Hh + base + pj0] = hh;
        if (phase) *(__half2*)&g_hs16[((size_t)b*Tt + tt)*Hh + base + pj0] = hh;
        if (t == 255){
            float2 lv = make_float2(hv[0], hv[1]);
            *(float2*)&lat[b*Hh + base + pj0] = lv;
        }
        __threadfence();
        __syncthreads();
        if (tid == 0) atomicExch((unsigned*)&pf[cb], (unsigned)(t + 1));
    }
}

// ---- head via WMMA: seq[m][n] = hs16[m].pw16[n] + pb[n]; BK=32 double-buffered ----
__global__ void k_head16(const float* __restrict__ pb, float* __restrict__ seq){
    extern __shared__ char dsm[];
    __half* As[2] = { (__half*)dsm,              (__half*)(dsm + 10240) };
    __half* Bs[2] = { (__half*)(dsm + 20480),    (__half*)(dsm + 25600) };
    float*  Cs    = (float*)dsm;

    int tid = threadIdx.x, wid = tid >> 5;
    int m0 = blockIdx.y * 128, n0 = blockIdx.x * 64;
    int wm = (wid & 3) * 32, wn = (wid >> 2) * 32;

    wmma::fragment<wmma::accumulator,16,16,16,float> acc[2][2];
    #pragma unroll
    for (int i=0;i<2;i++)
        #pragma unroll
        for (int j=0;j<2;j++) wmma::fill_fragment(acc[i][j], 0.f);

    const uint32_t* Hu = (const uint32_t*)g_hs16;
    const uint32_t* Pu = (const uint32_t*)g_pw16;

    {
        uint32_t* Au = (uint32_t*)As[0];
        uint32_t* Bu = (uint32_t*)Bs[0];
        #pragma unroll
        for (int q = 0; q < 8; q++){
            int idx = tid + q*256, r = idx >> 4, kp = idx & 15;
            Au[r*20 + kp] = Hu[(size_t)(m0 + r)*512 + kp];
        }
        #pragma unroll
        for (int q = 0; q < 4; q++){
            int idx = tid + q*256, r = idx >> 4, kp = idx & 15;
            Bu[r*20 + kp] = Pu[(size_t)(n0 + r)*512 + kp];
        }
    }
    __syncthreads();

    for (int kt = 0; kt < 32; kt++){
        int cur = kt & 1, nxt = cur ^ 1;
        uint32_t pfa[8], pfb[4];
        if (kt < 31){
            int kb = (kt+1)*16;
            #pragma unroll
            for (int q = 0; q < 8; q++){
                int idx = tid + q*256, r = idx >> 4, kp = idx & 15;
                pfa[q] = Hu[(size_t)(m0 + r)*512 + kb + kp];
            }
            #pragma unroll
            for (int q = 0; q < 4; q++){
                int idx = tid + q*256, r = idx >> 4, kp = idx & 15;
                pfb[q] = Pu[(size_t)(n0 + r)*512 + kb + kp];
            }
        }
        #pragma unroll
        for (int sub = 0; sub < 2; sub++){
            wmma::fragment<wmma::matrix_a,16,16,16,__half,wmma::row_major> af[2];
            wmma::fragment<wmma::matrix_b,16,16,16,__half,wmma::col_major> bf[2];
            wmma::load_matrix_sync(af[0], &As[cur][(wm     )*40 + sub*16], 40);
            wmma::load_matrix_sync(af[1], &As[cur][(wm + 16)*40 + sub*16], 40);
            wmma::load_matrix_sync(bf[0], &Bs[cur][(wn     )*40 + sub*16], 40);
            wmma::load_matrix_sync(bf[1], &Bs[cur][(wn + 16)*40 + sub*16], 40);
            #pragma unroll
            for (int i=0;i<2;i++)
                #pragma unroll
                for (int j=0;j<2;j++)
                    wmma::mma_sync(acc[i][j], af[i], bf[j], acc[i][j]);
        }
        if (kt < 31){
            uint32_t* Au = (uint32_t*)As[nxt];
            uint32_t* Bu = (uint32_t*)Bs[nxt];
            #pragma unroll
            for (int q = 0; q < 8; q++){
                int idx = tid + q*256, r = idx >> 4, kp = idx & 15;
                Au[r*20 + kp] = pfa[q];
            }
            #pragma unroll
            for (int q = 0; q < 4; q++){
                int idx = tid + q*256, r = idx >> 4, kp = idx & 15;
                Bu[r*20 + kp] = pfb[q];
            }
        }
        __syncthreads();
    }

    wmma::store_matrix_sync(&Cs[(wm     )*68 + wn     ], acc[0][0], 68, wmma::mem_row_major);
    wmma::store_matrix_sync(&Cs[(wm     )*68 + wn + 16], acc[0][1], 68, wmma::mem_row_major);
    wmma::store_matrix_sync(&Cs[(wm + 16)*68 + wn     ], acc[1][0], 68, wmma::mem_row_major);
    wmma::store_matrix_sync(&Cs[(wm + 16)*68 + wn + 16], acc[1][1], 68, wmma::mem_row_major);
    __syncthreads();

    #pragma unroll
    for (int q = 0; q < 32; q++){
        int e = tid + q*256;
        int r = e >> 6, cl = e & 63;
        int n = n0 + cl;
        if (n < Dd)
            seq[(size_t)(m0 + r)*Dd + n] = Cs[r*68 + cl] + pb[n];
    }
}

static float* symaddr(const void* sym){
    void* p = 0;
    cudaGetSymbolAddress(&p, sym);
    return (float*)p;
}

extern "C" void kernel_launch(void* const* d_in, const int* in_sizes, int n_in,
                              void* d_out, int out_size) {
    const float* inputs  = (const float*)d_in[0];
    const float* enc_Wih = (const float*)d_in[1];
    const float* enc_Whh = (const float*)d_in[2];
    const float* enc_b   = (const float*)d_in[3];
    const float* dec_Wih = (const float*)d_in[4];
    const float* dec_Whh = (const float*)d_in[5];
    const float* dec_b   = (const float*)d_in[6];
    const float* pred_W  = (const float*)d_in[7];
    const float* pred_b  = (const float*)d_in[8];

    float* lat = (float*)d_out;               // [1,B,H]
    float* seq = (float*)d_out + Bb*Hh;       // [B,T,D]

    float* gxe = symaddr(g_gx_enc);
    float* gxd = symaddr(g_gx_dec);
    __half* w16e = (__half*)symaddr(g_w16_enc);
    __half* w16d = (__half*)symaddr(g_w16_dec);

    k_init<<<(Bb*Hh + 255)/256, 256>>>();
    k_conv_x16<<<(TB*XP + 255)/256, 256>>>(inputs);
    k_conv_w16<<<(G4*XP + 255)/256, 256>>>(enc_Wih, w16e);
    k_conv_w16<<<(G4*XP + 255)/256, 256>>>(dec_Wih, w16d);
    k_conv_pw16<<<(448*Hh + 255)/256, 256>>>(pred_W);

    const int gsmem = 35840;
    dim3 gg(G4/64, TB/128);
    k_gates16<<<gg, 256, gsmem>>>(w16e, enc_b, gxe, 0);
    k_gates16<<<gg, 256, gsmem>>>(w16d, dec_b, gxd, 1);

    const int rsmem = (64 + 32)*HLD*2 + 32*68*4;   // 206,848
    cudaFuncSetAttribute(k_recur, cudaFuncAttributeMaxDynamicSharedMemorySize, rsmem);
    k_recur<<<NCTA, 256, rsmem>>>(enc_Whh, dec_Whh, lat);

    cudaFuncSetAttribute(k_head16, cudaFuncAttributeMaxDynamicSharedMemorySize, gsmem);
    dim3 hg((Dd + 63)/64, TB/128);
    k_head16<<<hg, 256, gsmem>>>(pred_b, seq);
}

// round 13
// speedup vs baseline: 6.3299x; 1.0002x over previous
#include <cuda_runtime.h>
#include <cuda_fp16.h>
#include <mma.h>
#include <stdint.h>
#include <math.h>

using namespace nvcuda;

#define Bb 64
#define Tt 256
#define Dd 409
#define XP 416     // padded K for x/Wih
#define Hh 1024
#define G4 4096
#define TB 16384   // B*T
#define NCTA 128
#define HLD 1032   // half lead dim in recurrence smem

__device__ float  g_gx_enc[(size_t)TB*G4];      // x@Wih^T (NO bias; added in recur)
__device__ float  g_gx_dec[(size_t)TB*G4];
__device__ __half g_hs16[(size_t)TB*Hh];        // decoder h fp16 (head input)
__device__ __half g_h16[2][Bb*Hh];              // ping-pong h, fp16
__device__ __half g_x16[(size_t)TB*XP];         // x fp16, K padded
__device__ __half g_w16_enc[(size_t)G4*XP];
__device__ __half g_w16_dec[(size_t)G4*XP];
__device__ __half g_pw16[(size_t)448*Hh];       // pred_W fp16, rows padded
__device__ unsigned g_pflag[2][64];
__device__ unsigned g_cflag[2][64];

__global__ void k_init(){
    int i = blockIdx.x*blockDim.x + threadIdx.x;
    if (i < Bb*Hh) g_h16[0][i] = __float2half_rn(0.f);
    if (blockIdx.x == 0 && threadIdx.x < 128){
        int s = threadIdx.x >> 6, c = threadIdx.x & 63;
        g_pflag[s][c] = 0u;
        g_cflag[s][c] = 0u;
    }
}

__global__ void k_conv_x16(const float* __restrict__ x){
    int i = blockIdx.x*blockDim.x + threadIdx.x;
    if (i >= TB*XP) return;
    int d = i % XP, m = i / XP;
    g_x16[i] = (d < Dd) ? __float2half_rn(x[(size_t)m*Dd + d]) : __float2half_rn(0.f);
}
__global__ void k_conv_w16(const float* __restrict__ w, __half* __restrict__ dst){
    int i = blockIdx.x*blockDim.x + threadIdx.x;
    if (i >= G4*XP) return;
    int d = i % XP, r = i / XP;
    dst[i] = (d < Dd) ? __float2half_rn(w[(size_t)r*Dd + d]) : __float2half_rn(0.f);
}
__global__ void k_conv_pw16(const float* __restrict__ w){
    int i = blockIdx.x*blockDim.x + threadIdx.x;
    if (i >= 448*Hh) return;
    int r = i >> 10;
    g_pw16[i] = (r < Dd) ? __float2half_rn(w[i]) : __float2half_rn(0.f);
}

// ---- gates v3: BM=128 BN=128, BK=32 double-buffered, direct global store.
// gx[m][n] = Xrow(m).Wih[n]   (bias added later in recurrence).
// 8 warps: wm2=wid>>1 (4 m-tiles of 32), wn2=wid&1 (2 n-tiles of 64); acc[2][4].
__global__ void k_gates16(const __half* __restrict__ W16,
                          float* __restrict__ gx, int shifted){
    extern __shared__ char dsm[];
    __half* As[2] = { (__half*)dsm,           (__half*)(dsm + 10240) };
    __half* Bs[2] = { (__half*)(dsm + 20480), (__half*)(dsm + 30720) };

    int tid = threadIdx.x, wid = tid >> 5;
    int m0 = blockIdx.y * 128, n0 = blockIdx.x * 128;
    int wm = (wid >> 1) * 32, wn = (wid & 1) * 64;

    wmma::fragment<wmma::accumulator,16,16,16,float> acc[2][4];
    #pragma unroll
    for (int i=0;i<2;i++)
        #pragma unroll
        for (int j=0;j<4;j++) wmma::fill_fragment(acc[i][j], 0.f);

    const uint32_t* Xu = (const uint32_t*)g_x16;
    const uint32_t* Wu = (const uint32_t*)W16;

    // load tile kt=0
    {
        uint32_t* Au = (uint32_t*)As[0];
        uint32_t* Bu = (uint32_t*)Bs[0];
        #pragma unroll
        for (int q = 0; q < 8; q++){
            int idx = tid + q*256, r = idx >> 4, kp = idx & 15;
            int m = m0 + r;
            uint32_t v = 0u;
            if (!shifted)            v = Xu[(size_t)m*208 + kp];
            else if ((m & 255) != 0) v = Xu[(size_t)(m-1)*208 + kp];
            Au[r*20 + kp] = v;
        }
        #pragma unroll
        for (int q = 0; q < 8; q++){
            int idx = tid + q*256, r = idx >> 4, kp = idx & 15;
            Bu[r*20 + kp] = Wu[(size_t)(n0 + r)*208 + kp];
        }
    }
    __syncthreads();

    for (int kt = 0; kt < 13; kt++){
        int cur = kt & 1, nxt = cur ^ 1;
        uint32_t pfa[8], pfb[8];
        if (kt < 12){
            int kb = (kt+1)*16;
            #pragma unroll
            for (int q = 0; q < 8; q++){
                int idx = tid + q*256, r = idx >> 4, kp = idx & 15;
                int m = m0 + r;
                uint32_t v = 0u;
                if (!shifted)            v = Xu[(size_t)m*208 + kb + kp];
                else if ((m & 255) != 0) v = Xu[(size_t)(m-1)*208 + kb + kp];
                pfa[q] = v;
            }
            #pragma unroll
            for (int q = 0; q < 8; q++){
                int idx = tid + q*256, r = idx >> 4, kp = idx & 15;
                pfb[q] = Wu[(size_t)(n0 + r)*208 + kb + kp];
            }
        }
        #pragma unroll
        for (int sub = 0; sub < 2; sub++){
            wmma::fragment<wmma::matrix_a,16,16,16,__half,wmma::row_major> af[2];
            wmma::fragment<wmma::matrix_b,16,16,16,__half,wmma::col_major> bf[4];
            #pragma unroll
            for (int i=0;i<2;i++)
                wmma::load_matrix_sync(af[i], &As[cur][(wm + i*16)*40 + sub*16], 40);
            #pragma unroll
            for (int j=0;j<4;j++)
                wmma::load_matrix_sync(bf[j], &Bs[cur][(wn + j*16)*40 + sub*16], 40);
            #pragma unroll
            for (int i=0;i<2;i++)
                #pragma unroll
                for (int j=0;j<4;j++)
                    wmma::mma_sync(acc[i][j], af[i], bf[j], acc[i][j]);
        }
        if (kt < 12){
            uint32_t* Au = (uint32_t*)As[nxt];
            uint32_t* Bu = (uint32_t*)Bs[nxt];
            #pragma unroll
            for (int q = 0; q < 8; q++){
                int idx = tid + q*256, r = idx >> 4, kp = idx & 15;
                Au[r*20 + kp] = pfa[q];
            }
            #pragma unroll
            for (int q = 0; q < 8; q++){
                int idx = tid + q*256, r = idx >> 4, kp = idx & 15;
                Bu[r*20 + kp] = pfb[q];
            }
        }
        __syncthreads();
    }

    // direct store to global (N=4096 fragment-exact; no staging, no bias)
    #pragma unroll
    for (int i=0;i<2;i++)
        #pragma unroll
        for (int j=0;j<4;j++)
            wmma::store_matrix_sync(&gx[(size_t)(m0 + wm + i*16)*G4 + n0 + wn + j*16],
                                    acc[i][j], G4, wmma::mem_row_major);
}

// ---- persistent recurrence v4: split-k pipelined gather, dual accumulators,
// bias folded in (gx has no bias). Distributed flag handshake per half. ----
__global__ void __launch_bounds__(256, 1) k_recur(
    const float* __restrict__ WhhE, const float* __restrict__ WhhD,
    const float* __restrict__ encB, const float* __restrict__ decB,
    float* __restrict__ lat)
{
    extern __shared__ char smc[];
    __half* Ws = (__half*)smc;                          // 64 x HLD
    __half* Hs = (__half*)(smc + 64*HLD*2);             // 32 x HLD
    float*  Gs = (float* )(smc + (64+32)*HLD*2);        // 32 x 68

    int tid = threadIdx.x;
    int wid = tid >> 5;
    int wm = wid >> 2, wn = wid & 3;
    int s    = blockIdx.x & 1;
    int cb   = blockIdx.x >> 1;
    int base = cb * 16;
    int boff = s * 32;

    int pb_ = tid >> 3;
    int pj0 = (tid & 7) * 2;

    volatile unsigned* pf = g_pflag[s];
    volatile unsigned* cf = g_cflag[s];

    for (int idx = tid; idx < 64*1024; idx += 256){
        int r = idx >> 10, k = idx & 1023;
        int grow = ((r >> 4) << 10) + base + (r & 15);
        Ws[r*HLD + k] = __float2half_rn(WhhE[(size_t)grow*1024 + k]);
    }

    // bias registers for phase 0
    float bv[8];
    #pragma unroll
    for (int g = 0; g < 4; g++){
        bv[2*g]   = encB[g*1024 + base + pj0];
        bv[2*g+1] = encB[g*1024 + base + pj0 + 1];
    }

    float c0 = 0.f, c1 = 0.f;
    __syncthreads();

    for (int t = 0; t < 512; t++){
        int phase = t >> 8, tt = t & 255;
        if (t == 256){
            __syncthreads();
            for (int idx = tid; idx < 64*1024; idx += 256){
                int r = idx >> 10, k = idx & 1023;
                int grow = ((r >> 4) << 10) + base + (r & 15);
                Ws[r*HLD + k] = __float2half_rn(WhhD[(size_t)grow*1024 + k]);
            }
            #pragma unroll
            for (int g = 0; g < 4; g++){
                bv[2*g]   = decB[g*1024 + base + pj0];
                bv[2*g+1] = decB[g*1024 + base + pj0 + 1];
            }
            __syncthreads();
        }
        const float* gxP = phase ? g_gx_dec : g_gx_enc;

        // forward wait: producers of my half published h for step t
        if (t > 0){
            if (tid < 64){ while (pf[tid] < (unsigned)t) { } }
            __syncthreads();
        }

        // prefetch gx gate quadruples
        float gxv[8];
        {
            const float* gxr = gxP + ((size_t)(boff + pb_)*Tt + tt)*G4;
            #pragma unroll
            for (int g = 0; g < 4; g++){
                float2 v = *(const float2*)&gxr[g*1024 + base + pj0];
                gxv[2*g]   = v.x;
                gxv[2*g+1] = v.y;
            }
        }

        const uint4* src = (const uint4*)g_h16[t & 1];
        uint4* dst = (uint4*)Hs;

        // gather half 0 (cols 0..511): 2048 uint4
        #pragma unroll
        for (int q = 0; q < 8; q++){
            int idx = tid + q*256, row = idx >> 6, c8 = idx & 63;
            dst[row*129 + c8] = __ldcg(&src[(size_t)(boff + row)*128 + c8]);
        }
        __syncthreads();

        // issue half-1 loads (latency hidden under half-0 MMA)
        uint4 pfh[8];
        #pragma unroll
        for (int q = 0; q < 8; q++){
            int idx = tid + q*256, row = idx >> 6, c8 = idx & 63;
            pfh[q] = __ldcg(&src[(size_t)(boff + row)*128 + 64 + c8]);
        }

        wmma::fragment<wmma::accumulator,16,16,16,float> a0, a1;
        wmma::fill_fragment(a0, 0.f);
        wmma::fill_fragment(a1, 0.f);

        // MMA half 0 (k 0..511), dual chains
        #pragma unroll 4
        for (int k = 0; k < 512; k += 32){
            wmma::fragment<wmma::matrix_a,16,16,16,__half,wmma::row_major> af;
            wmma::fragment<wmma::matrix_b,16,16,16,__half,wmma::col_major> bf;
            wmma::load_matrix_sync(af, &Hs[(wm*16)*HLD + k], HLD);
            wmma::load_matrix_sync(bf, &Ws[(wn*16)*HLD + k], HLD);
            wmma::mma_sync(a0, af, bf, a0);
            wmma::load_matrix_sync(af, &Hs[(wm*16)*HLD + k + 16], HLD);
            wmma::load_matrix_sync(bf, &Ws[(wn*16)*HLD + k + 16], HLD);
            wmma::mma_sync(a1, af, bf, a1);
        }
        __syncthreads();                 // everyone done reading Hs half-0 region? (only cols; half-1 writes don't touch half-0) -- barrier orders STS below vs MMA reads above
        #pragma unroll
        for (int q = 0; q < 8; q++){
            int idx = tid + q*256, row = idx >> 6, c8 = idx & 63;
            dst[row*129 + 64 + c8] = pfh[q];
        }
        __syncthreads();
        if (tid == 0) atomicExch((unsigned*)&cf[cb], (unsigned)(t + 1));  // done reading g_h16 buf

        // MMA half 1 (k 512..1023)
        #pragma unroll 4
        for (int k = 512; k < 1024; k += 32){
            wmma::fragment<wmma::matrix_a,16,16,16,__half,wmma::row_major> af;
            wmma::fragment<wmma::matrix_b,16,16,16,__half,wmma::col_major> bf;
            wmma::load_matrix_sync(af, &Hs[(wm*16)*HLD + k], HLD);
            wmma::load_matrix_sync(bf, &Ws[(wn*16)*HLD + k], HLD);
            wmma::mma_sync(a0, af, bf, a0);
            wmma::load_matrix_sync(af, &Hs[(wm*16)*HLD + k + 16], HLD);
            wmma::load_matrix_sync(bf, &Ws[(wn*16)*HLD + k + 16], HLD);
            wmma::mma_sync(a1, af, bf, a1);
        }
        #pragma unroll
        for (int e = 0; e < a0.num_elements; e++) a0.x[e] += a1.x[e];
        wmma::store_matrix_sync(&Gs[(wm*16)*68 + wn*16], a0, 68, wmma::mem_row_major);
        __syncthreads();

        // pointwise (bias added here now)
        int b = boff + pb_;
        float hv[2];
        #pragma unroll
        for (int p = 0; p < 2; p++){
            int j = pj0 + p;
            float iv = Gs[pb_*68 +      j] + gxv[0 + p] + bv[0 + p];
            float fv = Gs[pb_*68 + 16 + j] + gxv[2 + p] + bv[2 + p];
            float gv = Gs[pb_*68 + 32 + j] + gxv[4 + p] + bv[4 + p];
            float ov = Gs[pb_*68 + 48 + j] + gxv[6 + p] + bv[6 + p];
            float si = 1.f / (1.f + expf(-iv));
            float sf = 1.f / (1.f + expf(-fv));
            float so = 1.f / (1.f + expf(-ov));
            float cc = p ? c1 : c0;
            cc = sf * cc + si * tanhf(gv);
            hv[p] = so * tanhf(cc);
            if (p) c1 = cc; else c0 = cc;
        }

        // backward wait: consumers done reading the buffer I'm about to write
        if (t > 0){
            if (tid < 64){ while (cf[tid] < (unsigned)t) { } }
            __syncthreads();
        }

        __half2 hh = __floats2half2_rn(hv[0], hv[1]);
        *(__half2*)&g_h16[(t + 1) & 1][b*Hh + base + pj0] = hh;
        if (phase) *(__half2*)&g_hs16[((size_t)b*Tt + tt)*Hh + base + pj0] = hh;
        if (t == 255){
            float2 lv = make_float2(hv[0], hv[1]);
            *(float2*)&lat[b*Hh + base + pj0] = lv;
        }
        __threadfence();
        __syncthreads();
        if (tid == 0) atomicExch((unsigned*)&pf[cb], (unsigned)(t + 1));
    }
}

// ---- head via WMMA (unchanged from R12; passed) ----
__global__ void k_head16(const float* __restrict__ pb, float* __restrict__ seq){
    extern __shared__ char dsm[];
    __half* As[2] = { (__half*)dsm,              (__half*)(dsm + 10240) };
    __half* Bs[2] = { (__half*)(dsm + 20480),    (__half*)(dsm + 25600) };
    float*  Cs    = (float*)dsm;

    int tid = threadIdx.x, wid = tid >> 5;
    int m0 = blockIdx.y * 128, n0 = blockIdx.x * 64;
    int wm = (wid & 3) * 32, wn = (wid >> 2) * 32;

    wmma::fragment<wmma::accumulator,16,16,16,float> acc[2][2];
    #pragma unroll
    for (int i=0;i<2;i++)
        #pragma unroll
        for (int j=0;j<2;j++) wmma::fill_fragment(acc[i][j], 0.f);

    const uint32_t* Hu = (const uint32_t*)g_hs16;
    const uint32_t* Pu = (const uint32_t*)g_pw16;

    {
        uint32_t* Au = (uint32_t*)As[0];
        uint32_t* Bu = (uint32_t*)Bs[0];
        #pragma unroll
        for (int q = 0; q < 8; q++){
            int idx = tid + q*256, r = idx >> 4, kp = idx & 15;
            Au[r*20 + kp] = Hu[(size_t)(m0 + r)*512 + kp];
        }
        #pragma unroll
        for (int q = 0; q < 4; q++){
            int idx = tid + q*256, r = idx >> 4, kp = idx & 15;
            Bu[r*20 + kp] = Pu[(size_t)(n0 + r)*512 + kp];
        }
    }
    __syncthreads();

    for (int kt = 0; kt < 32; kt++){
        int cur = kt & 1, nxt = cur ^ 1;
        uint32_t pfa[8], pfb[4];
        if (kt < 31){
            int kb = (kt+1)*16;
            #pragma unroll
            for (int q = 0; q < 8; q++){
                int idx = tid + q*256, r = idx >> 4, kp = idx & 15;
                pfa[q] = Hu[(size_t)(m0 + r)*512 + kb + kp];
            }
            #pragma unroll
            for (int q = 0; q < 4; q++){
                int idx = tid + q*256, r = idx >> 4, kp = idx & 15;
                pfb[q] = Pu[(size_t)(n0 + r)*512 + kb + kp];
            }
        }
        #pragma unroll
        for (int sub = 0; sub < 2; sub++){
            wmma::fragment<wmma::matrix_a,16,16,16,__half,wmma::row_major> af[2];
            wmma::fragment<wmma::matrix_b,16,16,16,__half,wmma::col_major> bf[2];
            wmma::load_matrix_sync(af[0], &As[cur][(wm     )*40 + sub*16], 40);
            wmma::load_matrix_sync(af[1], &As[cur][(wm + 16)*40 + sub*16], 40);
            wmma::load_matrix_sync(bf[0], &Bs[cur][(wn     )*40 + sub*16], 40);
            wmma::load_matrix_sync(bf[1], &Bs[cur][(wn + 16)*40 + sub*16], 40);
            #pragma unroll
            for (int i=0;i<2;i++)
                #pragma unroll
                for (int j=0;j<2;j++)
                    wmma::mma_sync(acc[i][j], af[i], bf[j], acc[i][j]);
        }
        if (kt < 31){
            uint32_t* Au = (uint32_t*)As[nxt];
            uint32_t* Bu = (uint32_t*)Bs[nxt];
            #pragma unroll
            for (int q = 0; q < 8; q++){
                int idx = tid + q*256, r = idx >> 4, kp = idx & 15;
                Au[r*20 + kp] = pfa[q];
            }
            #pragma unroll
            for (int q = 0; q < 4; q++){
                int idx = tid + q*256, r = idx >> 4, kp = idx & 15;
                Bu[r*20 + kp] = pfb[q];
            }
        }
        __syncthreads();
    }

    wmma::store_matrix_sync(&Cs[(wm     )*68 + wn     ], acc[0][0], 68, wmma::mem_row_major);
    wmma::store_matrix_sync(&Cs[(wm     )*68 + wn + 16], acc[0][1], 68, wmma::mem_row_major);
    wmma::store_matrix_sync(&Cs[(wm + 16)*68 + wn     ], acc[1][0], 68, wmma::mem_row_major);
    wmma::store_matrix_sync(&Cs[(wm + 16)*68 + wn + 16], acc[1][1], 68, wmma::mem_row_major);
    __syncthreads();

    #pragma unroll
    for (int q = 0; q < 32; q++){
        int e = tid + q*256;
        int r = e >> 6, cl = e & 63;
        int n = n0 + cl;
        if (n < Dd)
            seq[(size_t)(m0 + r)*Dd + n] = Cs[r*68 + cl] + pb[n];
    }
}

static float* symaddr(const void* sym){
    void* p = 0;
    cudaGetSymbolAddress(&p, sym);
    return (float*)p;
}

extern "C" void kernel_launch(void* const* d_in, const int* in_sizes, int n_in,
                              void* d_out, int out_size) {
    const float* inputs  = (const float*)d_in[0];
    const float* enc_Wih = (const float*)d_in[1];
    const float* enc_Whh = (const float*)d_in[2];
    const float* enc_b   = (const float*)d_in[3];
    const float* dec_Wih = (const float*)d_in[4];
    const float* dec_Whh = (const float*)d_in[5];
    const float* dec_b   = (const float*)d_in[6];
    const float* pred_W  = (const float*)d_in[7];
    const float* pred_b  = (const float*)d_in[8];

    float* lat = (float*)d_out;               // [1,B,H]
    float* seq = (float*)d_out + Bb*Hh;       // [B,T,D]

    float* gxe = symaddr(g_gx_enc);
    float* gxd = symaddr(g_gx_dec);
    __half* w16e = (__half*)symaddr(g_w16_enc);
    __half* w16d = (__half*)symaddr(g_w16_dec);

    k_init<<<(Bb*Hh + 255)/256, 256>>>();
    k_conv_x16<<<(TB*XP + 255)/256, 256>>>(inputs);
    k_conv_w16<<<(G4*XP + 255)/256, 256>>>(enc_Wih, w16e);
    k_conv_w16<<<(G4*XP + 255)/256, 256>>>(dec_Wih, w16d);
    k_conv_pw16<<<(448*Hh + 255)/256, 256>>>(pred_W);

    // gates v3: BM=128 BN=128; smem = 4 x 10240 = 40960B
    const int gsmem = 40960;
    cudaFuncSetAttribute(k_gates16, cudaFuncAttributeMaxDynamicSharedMemorySize, gsmem);
    dim3 gg(G4/128, TB/128);
    k_gates16<<<gg, 256, gsmem>>>(w16e, gxe, 0);
    k_gates16<<<gg, 256, gsmem>>>(w16d, gxd, 1);

    const int rsmem = (64 + 32)*HLD*2 + 32*68*4;   // 206,848
    cudaFuncSetAttribute(k_recur, cudaFuncAttributeMaxDynamicSharedMemorySize, rsmem);
    k_recur<<<NCTA, 256, rsmem>>>(enc_Whh, dec_Whh, enc_b, dec_b, lat);

    const int hsmem = 35840;
    cudaFuncSetAttribute(k_head16, cudaFuncAttributeMaxDynamicSharedMemorySize, hsmem);
    dim3 hg((Dd + 63)/64, TB/128);
    k_head16<<<hg, 256, hsmem>>>(pred_b, seq);
}

// round 14
// speedup vs baseline: 6.4514x; 1.0192x over previous
#include <cuda_runtime.h>
#include <cuda_fp16.h>
#include <mma.h>
#include <stdint.h>
#include <math.h>

using namespace nvcuda;

#define Bb 64
#define Tt 256
#define Dd 409
#define XP 416     // padded K for x/Wih
#define Hh 1024
#define G4 4096
#define TB 16384   // B*T
#define NCTA 128
#define HLD 1032   // half lead dim in recurrence smem

__device__ float  g_gx_enc[(size_t)TB*G4];      // x@Wih^T (NO bias; added in recur)
__device__ float  g_gx_dec[(size_t)TB*G4];
__device__ __half g_hs16[(size_t)TB*Hh];        // decoder h fp16 (head input)
__device__ __half g_h16[2][Bb*Hh];              // ping-pong h, fp16
__device__ __half g_x16[(size_t)TB*XP];         // x fp16, K padded
__device__ __half g_w16_enc[(size_t)G4*XP];
__device__ __half g_w16_dec[(size_t)G4*XP];
__device__ __half g_pw16[(size_t)448*Hh];       // pred_W fp16, rows padded
__device__ unsigned g_pflag[2][64];
__device__ unsigned g_cflag[2][64];

__global__ void k_init(){
    int i = blockIdx.x*blockDim.x + threadIdx.x;
    if (i < Bb*Hh) g_h16[0][i] = __float2half_rn(0.f);
    if (blockIdx.x == 0 && threadIdx.x < 128){
        int s = threadIdx.x >> 6, c = threadIdx.x & 63;
        g_pflag[s][c] = 0u;
        g_cflag[s][c] = 0u;
    }
}

__global__ void k_conv_x16(const float* __restrict__ x){
    int i = blockIdx.x*blockDim.x + threadIdx.x;
    if (i >= TB*XP) return;
    int d = i % XP, m = i / XP;
    g_x16[i] = (d < Dd) ? __float2half_rn(x[(size_t)m*Dd + d]) : __float2half_rn(0.f);
}
__global__ void k_conv_w16(const float* __restrict__ w, __half* __restrict__ dst){
    int i = blockIdx.x*blockDim.x + threadIdx.x;
    if (i >= G4*XP) return;
    int d = i % XP, r = i / XP;
    dst[i] = (d < Dd) ? __float2half_rn(w[(size_t)r*Dd + d]) : __float2half_rn(0.f);
}
__global__ void k_conv_pw16(const float* __restrict__ w){
    int i = blockIdx.x*blockDim.x + threadIdx.x;
    if (i >= 448*Hh) return;
    int r = i >> 10;
    g_pw16[i] = (r < Dd) ? __float2half_rn(w[i]) : __float2half_rn(0.f);
}

// ---- gates v3 (unchanged from R13; passed): BM=128 BN=128, direct global store ----
__global__ void k_gates16(const __half* __restrict__ W16,
                          float* __restrict__ gx, int shifted){
    extern __shared__ char dsm[];
    __half* As[2] = { (__half*)dsm,           (__half*)(dsm + 10240) };
    __half* Bs[2] = { (__half*)(dsm + 20480), (__half*)(dsm + 30720) };

    int tid = threadIdx.x, wid = tid >> 5;
    int m0 = blockIdx.y * 128, n0 = blockIdx.x * 128;
    int wm = (wid >> 1) * 32, wn = (wid & 1) * 64;

    wmma::fragment<wmma::accumulator,16,16,16,float> acc[2][4];
    #pragma unroll
    for (int i=0;i<2;i++)
        #pragma unroll
        for (int j=0;j<4;j++) wmma::fill_fragment(acc[i][j], 0.f);

    const uint32_t* Xu = (const uint32_t*)g_x16;
    const uint32_t* Wu = (const uint32_t*)W16;

    {
        uint32_t* Au = (uint32_t*)As[0];
        uint32_t* Bu = (uint32_t*)Bs[0];
        #pragma unroll
        for (int q = 0; q < 8; q++){
            int idx = tid + q*256, r = idx >> 4, kp = idx & 15;
            int m = m0 + r;
            uint32_t v = 0u;
            if (!shifted)            v = Xu[(size_t)m*208 + kp];
            else if ((m & 255) != 0) v = Xu[(size_t)(m-1)*208 + kp];
            Au[r*20 + kp] = v;
        }
        #pragma unroll
        for (int q = 0; q < 8; q++){
            int idx = tid + q*256, r = idx >> 4, kp = idx & 15;
            Bu[r*20 + kp] = Wu[(size_t)(n0 + r)*208 + kp];
        }
    }
    __syncthreads();

    for (int kt = 0; kt < 13; kt++){
        int cur = kt & 1, nxt = cur ^ 1;
        uint32_t pfa[8], pfb[8];
        if (kt < 12){
            int kb = (kt+1)*16;
            #pragma unroll
            for (int q = 0; q < 8; q++){
                int idx = tid + q*256, r = idx >> 4, kp = idx & 15;
                int m = m0 + r;
                uint32_t v = 0u;
                if (!shifted)            v = Xu[(size_t)m*208 + kb + kp];
                else if ((m & 255) != 0) v = Xu[(size_t)(m-1)*208 + kb + kp];
                pfa[q] = v;
            }
            #pragma unroll
            for (int q = 0; q < 8; q++){
                int idx = tid + q*256, r = idx >> 4, kp = idx & 15;
                pfb[q] = Wu[(size_t)(n0 + r)*208 + kb + kp];
            }
        }
        #pragma unroll
        for (int sub = 0; sub < 2; sub++){
            wmma::fragment<wmma::matrix_a,16,16,16,__half,wmma::row_major> af[2];
            wmma::fragment<wmma::matrix_b,16,16,16,__half,wmma::col_major> bf[4];
            #pragma unroll
            for (int i=0;i<2;i++)
                wmma::load_matrix_sync(af[i], &As[cur][(wm + i*16)*40 + sub*16], 40);
            #pragma unroll
            for (int j=0;j<4;j++)
                wmma::load_matrix_sync(bf[j], &Bs[cur][(wn + j*16)*40 + sub*16], 40);
            #pragma unroll
            for (int i=0;i<2;i++)
                #pragma unroll
                for (int j=0;j<4;j++)
                    wmma::mma_sync(acc[i][j], af[i], bf[j], acc[i][j]);
        }
        if (kt < 12){
            uint32_t* Au = (uint32_t*)As[nxt];
            uint32_t* Bu = (uint32_t*)Bs[nxt];
            #pragma unroll
            for (int q = 0; q < 8; q++){
                int idx = tid + q*256, r = idx >> 4, kp = idx & 15;
                Au[r*20 + kp] = pfa[q];
            }
            #pragma unroll
            for (int q = 0; q < 8; q++){
                int idx = tid + q*256, r = idx >> 4, kp = idx & 15;
                Bu[r*20 + kp] = pfb[q];
            }
        }
        __syncthreads();
    }

    #pragma unroll
    for (int i=0;i<2;i++)
        #pragma unroll
        for (int j=0;j<4;j++)
            wmma::store_matrix_sync(&gx[(size_t)(m0 + wm + i*16)*G4 + n0 + wn + j*16],
                                    acc[i][j], G4, wmma::mem_row_major);
}

// ---- persistent recurrence v5: 512 threads, K split across warp groups.
// 16 warps: kh=wid>>3 (K half), wm=(wid&7)>>2 (m tile), wn=wid&3 (n tile).
// Partial G sums land in Gs0/Gs1; pointwise (threads <256, R12 mapping) adds them.
__global__ void __launch_bounds__(512, 1) k_recur(
    const float* __restrict__ WhhE, const float* __restrict__ WhhD,
    const float* __restrict__ encB, const float* __restrict__ decB,
    float* __restrict__ lat)
{
    extern __shared__ char smc[];
    __half* Ws  = (__half*)smc;                          // 64 x HLD
    __half* Hs  = (__half*)(smc + 64*HLD*2);             // 32 x HLD
    float*  Gs0 = (float* )(smc + 96*HLD*2);             // 32 x 68
    float*  Gs1 = Gs0 + 32*68;                           // 32 x 68

    int tid = threadIdx.x;
    int wid = tid >> 5;
    int kh = wid >> 3;           // 0..1 (K half)
    int wm = (wid & 7) >> 2;     // 0..1
    int wn = wid & 3;            // 0..3
    int s    = blockIdx.x & 1;
    int cb   = blockIdx.x >> 1;
    int base = cb * 16;
    int boff = s * 32;

    int pw  = (tid < 256);
    int pb_ = tid >> 3;          // valid for tid<256: 0..31
    int pj0 = (tid & 7) * 2;

    volatile unsigned* pf = g_pflag[s];
    volatile unsigned* cf = g_cflag[s];

    for (int idx = tid; idx < 64*1024; idx += 512){
        int r = idx >> 10, k = idx & 1023;
        int grow = ((r >> 4) << 10) + base + (r & 15);
        Ws[r*HLD + k] = __float2half_rn(WhhE[(size_t)grow*1024 + k]);
    }

    float bv[8];
    if (pw){
        #pragma unroll
        for (int g = 0; g < 4; g++){
            bv[2*g]   = encB[g*1024 + base + pj0];
            bv[2*g+1] = encB[g*1024 + base + pj0 + 1];
        }
    }

    float c0 = 0.f, c1 = 0.f;
    __syncthreads();

    for (int t = 0; t < 512; t++){
        int phase = t >> 8, tt = t & 255;
        if (t == 256){
            __syncthreads();
            for (int idx = tid; idx < 64*1024; idx += 512){
                int r = idx >> 10, k = idx & 1023;
                int grow = ((r >> 4) << 10) + base + (r & 15);
                Ws[r*HLD + k] = __float2half_rn(WhhD[(size_t)grow*1024 + k]);
            }
            if (pw){
                #pragma unroll
                for (int g = 0; g < 4; g++){
                    bv[2*g]   = decB[g*1024 + base + pj0];
                    bv[2*g+1] = decB[g*1024 + base + pj0 + 1];
                }
            }
            __syncthreads();
        }
        const float* gxP = phase ? g_gx_dec : g_gx_enc;

        // forward wait: producers of my half published h for step t
        if (t > 0){
            if (tid < 64){ while (pf[tid] < (unsigned)t) { } }
            __syncthreads();
        }

        // prefetch gx gate quadruples (pointwise threads only)
        float gxv[8];
        if (pw){
            const float* gxr = gxP + ((size_t)(boff + pb_)*Tt + tt)*G4;
            #pragma unroll
            for (int g = 0; g < 4; g++){
                float2 v = *(const float2*)&gxr[g*1024 + base + pj0];
                gxv[2*g]   = v.x;
                gxv[2*g+1] = v.y;
            }
        }

        // gather 32 batch rows of h (fp16) -> smem (64KB, one burst)
        {
            const uint4* src = (const uint4*)g_h16[t & 1];
            uint4* dst = (uint4*)Hs;
            #pragma unroll
            for (int q = 0; q < 8; q++){
                int idx = tid + q*512;           // 4096 uint4 = 32 x 128
                int row = idx >> 7, c8 = idx & 127;
                dst[row*129 + c8] = __ldcg(&src[(size_t)(boff + row)*128 + c8]);
            }
        }
        __syncthreads();
        if (tid == 0) atomicExch((unsigned*)&cf[cb], (unsigned)(t + 1));

        // G[32x64] partial: this warp covers K range [kh*512, kh*512+512)
        {
            wmma::fragment<wmma::accumulator,16,16,16,float> a0, a1;
            wmma::fill_fragment(a0, 0.f);
            wmma::fill_fragment(a1, 0.f);
            int k0 = kh * 512;
            #pragma unroll 4
            for (int k = k0; k < k0 + 512; k += 32){
                wmma::fragment<wmma::matrix_a,16,16,16,__half,wmma::row_major> af;
                wmma::fragment<wmma::matrix_b,16,16,16,__half,wmma::col_major> bf;
                wmma::load_matrix_sync(af, &Hs[(wm*16)*HLD + k], HLD);
                wmma::load_matrix_sync(bf, &Ws[(wn*16)*HLD + k], HLD);
                wmma::mma_sync(a0, af, bf, a0);
                wmma::load_matrix_sync(af, &Hs[(wm*16)*HLD + k + 16], HLD);
                wmma::load_matrix_sync(bf, &Ws[(wn*16)*HLD + k + 16], HLD);
                wmma::mma_sync(a1, af, bf, a1);
            }
            #pragma unroll
            for (int e = 0; e < a0.num_elements; e++) a0.x[e] += a1.x[e];
            float* Gdst = kh ? Gs1 : Gs0;
            wmma::store_matrix_sync(&Gdst[(wm*16)*68 + wn*16], a0, 68, wmma::mem_row_major);
        }
        __syncthreads();

        // pointwise (threads <256; same ownership/registers as R12)
        float hv[2];
        int b = boff + pb_;
        if (pw){
            #pragma unroll
            for (int p = 0; p < 2; p++){
                int j = pj0 + p;
                float iv = (Gs0[pb_*68 +      j] + Gs1[pb_*68 +      j]) + gxv[0 + p] + bv[0 + p];
                float fv = (Gs0[pb_*68 + 16 + j] + Gs1[pb_*68 + 16 + j]) + gxv[2 + p] + bv[2 + p];
                float gv = (Gs0[pb_*68 + 32 + j] + Gs1[pb_*68 + 32 + j]) + gxv[4 + p] + bv[4 + p];
                float ov = (Gs0[pb_*68 + 48 + j] + Gs1[pb_*68 + 48 + j]) + gxv[6 + p] + bv[6 + p];
                float si = 1.f / (1.f + expf(-iv));
                float sf = 1.f / (1.f + expf(-fv));
                float so = 1.f / (1.f + expf(-ov));
                float cc = p ? c1 : c0;
                cc = sf * cc + si * tanhf(gv);
                hv[p] = so * tanhf(cc);
                if (p) c1 = cc; else c0 = cc;
            }
        }

        // backward wait: consumers done reading the buffer I'm about to write
        if (t > 0){
            if (tid < 64){ while (cf[tid] < (unsigned)t) { } }
            __syncthreads();
        }

        if (pw){
            __half2 hh = __floats2half2_rn(hv[0], hv[1]);
            *(__half2*)&g_h16[(t + 1) & 1][b*Hh + base + pj0] = hh;
            if (phase) *(__half2*)&g_hs16[((size_t)b*Tt + tt)*Hh + base + pj0] = hh;
            if (t == 255){
                float2 lv = make_float2(hv[0], hv[1]);
                *(float2*)&lat[b*Hh + base + pj0] = lv;
            }
        }
        __threadfence();
        __syncthreads();
        if (tid == 0) atomicExch((unsigned*)&pf[cb], (unsigned)(t + 1));
    }
}

// ---- head via WMMA (unchanged; passed) ----
__global__ void k_head16(const float* __restrict__ pb, float* __restrict__ seq){
    extern __shared__ char dsm[];
    __half* As[2] = { (__half*)dsm,              (__half*)(dsm + 10240) };
    __half* Bs[2] = { (__half*)(dsm + 20480),    (__half*)(dsm + 25600) };
    float*  Cs    = (float*)dsm;

    int tid = threadIdx.x, wid = tid >> 5;
    int m0 = blockIdx.y * 128, n0 = blockIdx.x * 64;
    int wm = (wid & 3) * 32, wn = (wid >> 2) * 32;

    wmma::fragment<wmma::accumulator,16,16,16,float> acc[2][2];
    #pragma unroll
    for (int i=0;i<2;i++)
        #pragma unroll
        for (int j=0;j<2;j++) wmma::fill_fragment(acc[i][j], 0.f);

    const uint32_t* Hu = (const uint32_t*)g_hs16;
    const uint32_t* Pu = (const uint32_t*)g_pw16;

    {
        uint32_t* Au = (uint32_t*)As[0];
        uint32_t* Bu = (uint32_t*)Bs[0];
        #pragma unroll
        for (int q = 0; q < 8; q++){
            int idx = tid + q*256, r = idx >> 4, kp = idx & 15;
            Au[r*20 + kp] = Hu[(size_t)(m0 + r)*512 + kp];
        }
        #pragma unroll
        for (int q = 0; q < 4; q++){
            int idx = tid + q*256, r = idx >> 4, kp = idx & 15;
            Bu[r*20 + kp] = Pu[(size_t)(n0 + r)*512 + kp];
        }
    }
    __syncthreads();

    for (int kt = 0; kt < 32; kt++){
        int cur = kt & 1, nxt = cur ^ 1;
        uint32_t pfa[8], pfb[4];
        if (kt < 31){
            int kb = (kt+1)*16;
            #pragma unroll
            for (int q = 0; q < 8; q++){
                int idx = tid + q*256, r = idx >> 4, kp = idx & 15;
                pfa[q] = Hu[(size_t)(m0 + r)*512 + kb + kp];
            }
            #pragma unroll
            for (int q = 0; q < 4; q++){
                int idx = tid + q*256, r = idx >> 4, kp = idx & 15;
                pfb[q] = Pu[(size_t)(n0 + r)*512 + kb + kp];
            }
        }
        #pragma unroll
        for (int sub = 0; sub < 2; sub++){
            wmma::fragment<wmma::matrix_a,16,16,16,__half,wmma::row_major> af[2];
            wmma::fragment<wmma::matrix_b,16,16,16,__half,wmma::col_major> bf[2];
            wmma::load_matrix_sync(af[0], &As[cur][(wm     )*40 + sub*16], 40);
            wmma::load_matrix_sync(af[1], &As[cur][(wm + 16)*40 + sub*16], 40);
            wmma::load_matrix_sync(bf[0], &Bs[cur][(wn     )*40 + sub*16], 40);
            wmma::load_matrix_sync(bf[1], &Bs[cur][(wn + 16)*40 + sub*16], 40);
            #pragma unroll
            for (int i=0;i<2;i++)
                #pragma unroll
                for (int j=0;j<2;j++)
                    wmma::mma_sync(acc[i][j], af[i], bf[j], acc[i][j]);
        }
        if (kt < 31){
            uint32_t* Au = (uint32_t*)As[nxt];
            uint32_t* Bu = (uint32_t*)Bs[nxt];
            #pragma unroll
            for (int q = 0; q < 8; q++){
                int idx = tid + q*256, r = idx >> 4, kp = idx & 15;
                Au[r*20 + kp] = pfa[q];
            }
            #pragma unroll
            for (int q = 0; q < 4; q++){
                int idx = tid + q*256, r = idx >> 4, kp = idx & 15;
                Bu[r*20 + kp] = pfb[q];
            }
        }
        __syncthreads();
    }

    wmma::store_matrix_sync(&Cs[(wm     )*68 + wn     ], acc[0][0], 68, wmma::mem_row_major);
    wmma::store_matrix_sync(&Cs[(wm     )*68 + wn + 16], acc[0][1], 68, wmma::mem_row_major);
    wmma::store_matrix_sync(&Cs[(wm + 16)*68 + wn     ], acc[1][0], 68, wmma::mem_row_major);
    wmma::store_matrix_sync(&Cs[(wm + 16)*68 + wn + 16], acc[1][1], 68, wmma::mem_row_major);
    __syncthreads();

    #pragma unroll
    for (int q = 0; q < 32; q++){
        int e = tid + q*256;
        int r = e >> 6, cl = e & 63;
        int n = n0 + cl;
        if (n < Dd)
            seq[(size_t)(m0 + r)*Dd + n] = Cs[r*68 + cl] + pb[n];
    }
}

static float* symaddr(const void* sym){
    void* p = 0;
    cudaGetSymbolAddress(&p, sym);
    return (float*)p;
}

extern "C" void kernel_launch(void* const* d_in, const int* in_sizes, int n_in,
                              void* d_out, int out_size) {
    const float* inputs  = (const float*)d_in[0];
    const float* enc_Wih = (const float*)d_in[1];
    const float* enc_Whh = (const float*)d_in[2];
    const float* enc_b   = (const float*)d_in[3];
    const float* dec_Wih = (const float*)d_in[4];
    const float* dec_Whh = (const float*)d_in[5];
    const float* dec_b   = (const float*)d_in[6];
    const float* pred_W  = (const float*)d_in[7];
    const float* pred_b  = (const float*)d_in[8];

    float* lat = (float*)d_out;               // [1,B,H]
    float* seq = (float*)d_out + Bb*Hh;       // [B,T,D]

    float* gxe = symaddr(g_gx_enc);
    float* gxd = symaddr(g_gx_dec);
    __half* w16e = (__half*)symaddr(g_w16_enc);
    __half* w16d = (__half*)symaddr(g_w16_dec);

    k_init<<<(Bb*Hh + 255)/256, 256>>>();
    k_conv_x16<<<(TB*XP + 255)/256, 256>>>(inputs);
    k_conv_w16<<<(G4*XP + 255)/256, 256>>>(enc_Wih, w16e);
    k_conv_w16<<<(G4*XP + 255)/256, 256>>>(dec_Wih, w16d);
    k_conv_pw16<<<(448*Hh + 255)/256, 256>>>(pred_W);

    const int gsmem = 40960;
    cudaFuncSetAttribute(k_gates16, cudaFuncAttributeMaxDynamicSharedMemorySize, gsmem);
    dim3 gg(G4/128, TB/128);
    k_gates16<<<gg, 256, gsmem>>>(w16e, gxe, 0);
    k_gates16<<<gg, 256, gsmem>>>(w16d, gxd, 1);

    // recurrence v5: 96 x HLD halves + two 32x68 fp32 G buffers = 215,552B
    const int rsmem = 96*HLD*2 + 2*32*68*4;
    cudaFuncSetAttribute(k_recur, cudaFuncAttributeMaxDynamicSharedMemorySize, rsmem);
    k_recur<<<NCTA, 512, rsmem>>>(enc_Whh, dec_Whh, enc_b, dec_b, lat);

    const int hsmem = 35840;
    cudaFuncSetAttribute(k_head16, cudaFuncAttributeMaxDynamicSharedMemorySize, hsmem);
    dim3 hg((Dd + 63)/64, TB/128);
    k_head16<<<hg, 256, hsmem>>>(pred_b, seq);
}